// round 8
// baseline (speedup 1.0000x reference)
#include <cuda_runtime.h>
#include <cuda_bf16.h>
#include <cuda_fp16.h>
#include <cstdint>

// ---------------------------------------------------------------------------
// GCN: 3x (pointwise -> bf16x3 mma.sync GEMM -> CSR gather-sum) + mean pool
// GEMM first (row scaling commutes with @W; segment-sum is linear).
// Aggregation is PULL-based over a per-launch CSR (dst-sorted edges).
// R7->R8: launch order puts GEMM1 at index 4 (ncu capture slot); scanB+scanC
// fused into scanBC. Gather and GEMM bodies unchanged from R7 (best).
// ---------------------------------------------------------------------------

#define MAX_NODES 100000
#define MAX_EDGES 1600000
#define MAX_FEATS 128
#define SCAN_BS 512

__device__ __half g_X[MAX_NODES * MAX_FEATS];   // GEMM outputs, fp16 (gather input)
__device__ float  g_AGG[MAX_NODES * MAX_FEATS]; // gathered sums, fp32
__device__ float  g_outnorm[MAX_NODES];
__device__ float  g_innorm[MAX_NODES];
__device__ int    g_indeg[MAX_NODES];
__device__ int    g_outdeg[MAX_NODES];
__device__ int    g_rowptr[MAX_NODES + 1];
__device__ int    g_fill[MAX_NODES];
__device__ int    g_col[MAX_EDGES];
__device__ int    g_bsums[(MAX_NODES + SCAN_BS - 1) / SCAN_BS];

// ----------------------------- helpers -------------------------------------

__device__ __forceinline__ uint32_t smem_u32(const void* p) {
    uint32_t a;
    asm("{ .reg .u64 t; cvta.to.shared.u64 t, %1; cvt.u32.u64 %0, t; }" : "=r"(a) : "l"(p));
    return a;
}

__device__ __forceinline__ void ldsm_x4(uint32_t* r, uint32_t addr) {
    asm volatile("ldmatrix.sync.aligned.m8n8.x4.shared.b16 {%0,%1,%2,%3}, [%4];"
                 : "=r"(r[0]), "=r"(r[1]), "=r"(r[2]), "=r"(r[3]) : "r"(addr));
}

__device__ __forceinline__ void mma_bf16(float* d, const uint32_t* a, const uint32_t* b) {
    asm volatile("mma.sync.aligned.m16n8k16.row.col.f32.bf16.bf16.f32 "
                 "{%0,%1,%2,%3}, {%4,%5,%6,%7}, {%8,%9}, {%0,%1,%2,%3};"
                 : "+f"(d[0]), "+f"(d[1]), "+f"(d[2]), "+f"(d[3])
                 : "r"(a[0]), "r"(a[1]), "r"(a[2]), "r"(a[3]), "r"(b[0]), "r"(b[1]));
}

__device__ __forceinline__ void split2(float x, float y, uint32_t& hi, uint32_t& lo) {
    __nv_bfloat162 h = __floats2bfloat162_rn(x, y);
    float rx = x - __bfloat162float(h.x);
    float ry = y - __bfloat162float(h.y);
    __nv_bfloat162 l = __floats2bfloat162_rn(rx, ry);
    hi = reinterpret_cast<uint32_t&>(h);
    lo = reinterpret_cast<uint32_t&>(l);
}

__device__ __forceinline__ void split1(float x, uint16_t& hi, uint16_t& lo) {
    __nv_bfloat16 h = __float2bfloat16_rn(x);
    float r = x - __bfloat162float(h);
    __nv_bfloat16 l = __float2bfloat16_rn(r);
    hi = reinterpret_cast<uint16_t&>(h);
    lo = reinterpret_cast<uint16_t&>(l);
}

// --------------------------- CSR construction ------------------------------

__global__ void zero_int2_kernel(int* __restrict__ a, int* __restrict__ b, int n) {
    int i = blockIdx.x * blockDim.x + threadIdx.x;
    if (i < n) { a[i] = 0; b[i] = 0; }
}

__global__ void hist_kernel(const int* __restrict__ src, const int* __restrict__ dst,
                            int* __restrict__ outdeg, int* __restrict__ indeg, int E) {
    int i = blockIdx.x * blockDim.x + threadIdx.x;
    if (i < E) {
        atomicAdd(outdeg + src[i], 1);
        atomicAdd(indeg + dst[i], 1);
    }
}

__global__ void norm_kernel(const int* __restrict__ od, const int* __restrict__ id,
                            float* __restrict__ onrm, float* __restrict__ inrm, int n) {
    int i = blockIdx.x * blockDim.x + threadIdx.x;
    if (i < n) {
        onrm[i] = rsqrtf(fmaxf((float)od[i], 1.0f));
        inrm[i] = rsqrtf(fmaxf((float)id[i], 1.0f));
    }
}

__global__ void scanA_kernel(const int* __restrict__ deg, int* __restrict__ rowptr,
                             int* __restrict__ bsums, int n) {
    __shared__ int sh[SCAN_BS];
    int t = threadIdx.x;
    int i = blockIdx.x * SCAN_BS + t;
    int v = (i < n) ? deg[i] : 0;
    sh[t] = v;
    __syncthreads();
#pragma unroll
    for (int off = 1; off < SCAN_BS; off <<= 1) {
        int x = (t >= off) ? sh[t - off] : 0;
        __syncthreads();
        sh[t] += x;
        __syncthreads();
    }
    if (i < n) rowptr[i] = sh[t] - v;
    if (t == SCAN_BS - 1) bsums[blockIdx.x] = sh[t];
}

// Fused scanB+scanC: every block redundantly prefix-sums the (<=256) block
// sums in smem, then applies its offset and writes rowptr + fill cursors.
__global__ void scanBC_kernel(int* __restrict__ rowptr, int* __restrict__ fill,
                              const int* __restrict__ bsums, int nb, int n, int E) {
    __shared__ int pref[256];
    int t = threadIdx.x;
    int v = (t < nb) ? bsums[t] : 0;
    pref[t] = v;
    __syncthreads();
#pragma unroll
    for (int off = 1; off < 256; off <<= 1) {
        int x = (t >= off) ? pref[t - off] : 0;
        __syncthreads();
        pref[t] += x;
        __syncthreads();
    }
    // pref[b] now holds inclusive sum; exclusive = pref[b] - bsums[b]
    int i = blockIdx.x * blockDim.x + t;
    if (i < n) {
        int b = i / SCAN_BS;
        int excl = pref[b] - bsums[b];
        int r = rowptr[i] + excl;
        rowptr[i] = r;
        fill[i] = r;
    }
    if (i == 0) rowptr[n] = E;
}

__global__ void fill_kernel(const int* __restrict__ src, const int* __restrict__ dst,
                            int* __restrict__ fill, int* __restrict__ col, int E) {
    int i = blockIdx.x * blockDim.x + threadIdx.x;
    if (i < E) {
        int p = atomicAdd(fill + dst[i], 1);
        col[p] = src[i];
    }
}

// --------------------------- bf16x3 GEMM -----------------------------------
// X[M,N] (fp16) = f(A[M,K]) @ W[K,N], CTA tile 128 x N, K chunks of 32.
// MODE 0: f(a)[r,k] = a[r,k] * outnorm[r]
// MODE 1: f(a)[r,k] = relu(a[r,k]*innorm[r] + bprev[k]) * outnorm[r]
// bf16x3: D = Ah@Bh + Ah@Bl + Al@Bh, fp32 accum (mma.sync m16n8k16).

template<int K, int N, int MODE>
__global__ __launch_bounds__(256)
void gemm_mma_kernel(const float* __restrict__ A, const float* __restrict__ W,
                     const float* __restrict__ bprev,
                     const float* __restrict__ outnorm, const float* __restrict__ innorm,
                     __half* __restrict__ X, int M) {
    constexpr int BK = 32;
    constexpr int NCHUNK = K / BK;
    constexpr int WN = N / 2;
    constexpr int NT = WN / 8;
    constexpr int MT = 2;
    constexpr int P = 40;            // smem pitch in bf16 (80B, LDSM-clean)
    constexpr int A_HI = 0;
    constexpr int A_LO = 128 * P * 2;
    constexpr int W_HI = 2 * A_LO;
    constexpr int W_SZ = N * P * 2;
    constexpr int W_LO = W_HI + W_SZ;
    constexpr int BUFS = W_LO + W_SZ;
    constexpr int WE = N / 8;
    constexpr int LOGN = (N == 128) ? 7 : 6;

    extern __shared__ char smem[];
    const uint32_t sb = smem_u32(smem);
    const int tid = threadIdx.x;
    const int lane = tid & 31;
    const int wid = tid >> 5;
    const int warp_m = wid >> 1;
    const int warp_n = wid & 1;
    const int row0 = blockIdx.x * 128;

    const int arow = tid & 127;
    const int ahalf = tid >> 7;
    const int grow = row0 + arow;
    const bool valid = grow < M;
    const float on  = valid ? outnorm[grow] : 0.f;
    const float inn = (MODE == 1 && valid) ? innorm[grow] : 0.f;

    const int a_r = warp_m * 32 + ((lane >> 3) & 1) * 8 + (lane & 7);
    const int a_k = (lane >> 4) * 8;
    const int b_n = warp_n * WN + (lane >> 4) * 8 + (lane & 7);
    const int b_k = ((lane >> 3) & 1) * 8;

    float acc[MT][NT][4];
#pragma unroll
    for (int i = 0; i < MT; i++)
#pragma unroll
        for (int j = 0; j < NT; j++)
#pragma unroll
            for (int q = 0; q < 4; q++) acc[i][j][q] = 0.f;

    float4 av[4];
    float wv[WE];

    auto load_g = [&](int c) {
        const int kc = c * BK;
#pragma unroll
        for (int q = 0; q < 4; q++) {
            const int col = ahalf * 16 + q * 4;
            float4 v = make_float4(0.f, 0.f, 0.f, 0.f);
            if (valid) {
                v = *reinterpret_cast<const float4*>(A + (size_t)grow * K + kc + col);
                if (MODE == 0) {
                    v.x *= on; v.y *= on; v.z *= on; v.w *= on;
                } else {
                    float4 b = *reinterpret_cast<const float4*>(bprev + kc + col);
                    v.x = fmaxf(fmaf(v.x, inn, b.x), 0.f) * on;
                    v.y = fmaxf(fmaf(v.y, inn, b.y), 0.f) * on;
                    v.z = fmaxf(fmaf(v.z, inn, b.z), 0.f) * on;
                    v.w = fmaxf(fmaf(v.w, inn, b.w), 0.f) * on;
                }
            }
            av[q] = v;
        }
#pragma unroll
        for (int e = 0; e < WE; e++) {
            const int elem = tid + e * 256;
            const int n = elem & (N - 1);
            const int kk = elem >> LOGN;
            wv[e] = __ldg(W + (size_t)(kc + kk) * N + n);
        }
    };

    auto store_s = [&](int buf) {
        char* base = smem + buf * BUFS;
#pragma unroll
        for (int q = 0; q < 4; q++) {
            const int col = ahalf * 16 + q * 4;
            uint32_t h01, l01, h23, l23;
            split2(av[q].x, av[q].y, h01, l01);
            split2(av[q].z, av[q].w, h23, l23);
            const uint32_t off = (uint32_t)arow * (P * 2) + col * 2;
            *reinterpret_cast<uint2*>(base + A_HI + off) = make_uint2(h01, h23);
            *reinterpret_cast<uint2*>(base + A_LO + off) = make_uint2(l01, l23);
        }
#pragma unroll
        for (int e = 0; e < WE; e++) {
            const int elem = tid + e * 256;
            const int n = elem & (N - 1);
            const int kk = elem >> LOGN;
            uint16_t h, l;
            split1(wv[e], h, l);
            const uint32_t off = (uint32_t)n * (P * 2) + kk * 2;
            *reinterpret_cast<uint16_t*>(base + W_HI + off) = h;
            *reinterpret_cast<uint16_t*>(base + W_LO + off) = l;
        }
    };

    auto compute = [&](int buf) {
        const uint32_t ab = sb + buf * BUFS;
#pragma unroll
        for (int ks = 0; ks < 2; ks++) {
            uint32_t ah[MT][4], al[MT][4];
#pragma unroll
            for (int i = 0; i < MT; i++) {
                const uint32_t addr = ab + A_HI +
                    (uint32_t)(a_r + i * 16) * (P * 2) + (a_k + ks * 16) * 2;
                ldsm_x4(ah[i], addr);
                ldsm_x4(al[i], addr + A_LO);
            }
#pragma unroll
            for (int p = 0; p < NT / 2; p++) {
                uint32_t bh[4], bl[4];
                const uint32_t baddr = ab + W_HI +
                    (uint32_t)(b_n + p * 16) * (P * 2) + (b_k + ks * 16) * 2;
                ldsm_x4(bh, baddr);
                ldsm_x4(bl, baddr + W_SZ);
#pragma unroll
                for (int i = 0; i < MT; i++)
#pragma unroll
                    for (int jj = 0; jj < 2; jj++) {
                        float* d = acc[i][p * 2 + jj];
                        mma_bf16(d, ah[i], bh + jj * 2);
                        mma_bf16(d, ah[i], bl + jj * 2);
                        mma_bf16(d, al[i], bh + jj * 2);
                    }
            }
        }
    };

    load_g(0);
    store_s(0);
    __syncthreads();

    for (int c = 0; c < NCHUNK; c++) {
        if (c + 1 < NCHUNK) load_g(c + 1);
        compute(c & 1);
        if (c + 1 < NCHUNK) store_s((c + 1) & 1);
        __syncthreads();
    }

    // epilogue: fp32 acc -> fp16 X
#pragma unroll
    for (int i = 0; i < MT; i++) {
        const int r0 = row0 + warp_m * 32 + i * 16 + (lane >> 2);
#pragma unroll
        for (int j = 0; j < NT; j++) {
            const int n0 = warp_n * WN + j * 8 + (lane & 3) * 2;
            if (r0 < M)
                *reinterpret_cast<__half2*>(X + (size_t)r0 * N + n0) =
                    __floats2half2_rn(acc[i][j][0], acc[i][j][1]);
            if (r0 + 8 < M)
                *reinterpret_cast<__half2*>(X + (size_t)(r0 + 8) * N + n0) =
                    __floats2half2_rn(acc[i][j][2], acc[i][j][3]);
        }
    }
}

// ------------------------------ CSR gather ---------------------------------
// AGG[n] (fp32) = sum over e in [rowptr[n], rowptr[n+1]) of X[col[e]] (fp16)
// D/8 lanes per node; each lane loads 16B = 8 halves per edge.
// 2-edge unroll with 2 independent accumulator sets.

template<int D>
__global__ __launch_bounds__(256)
void gather_kernel(const __half* __restrict__ X, const int* __restrict__ rowptr,
                   const int* __restrict__ col, float* __restrict__ AGG, int Nn) {
    constexpr int LPN = D / 8;   // 16 for D=128, 8 for D=64
    int t = blockIdx.x * blockDim.x + threadIdx.x;
    int node = t / LPN;
    if (node >= Nn) return;
    int c = (t % LPN) * 8;
    int beg = __ldg(rowptr + node);
    int end = __ldg(rowptr + node + 1);

    float a0[8], a1[8];
#pragma unroll
    for (int q = 0; q < 8; q++) { a0[q] = 0.f; a1[q] = 0.f; }

    int e = beg;
    for (; e + 1 < end; e += 2) {
        int s0 = __ldg(col + e);
        int s1 = __ldg(col + e + 1);
        uint4 u0 = __ldg(reinterpret_cast<const uint4*>(X + (size_t)s0 * D + c));
        uint4 u1 = __ldg(reinterpret_cast<const uint4*>(X + (size_t)s1 * D + c));
        const __half2* h0 = reinterpret_cast<const __half2*>(&u0);
        const __half2* h1 = reinterpret_cast<const __half2*>(&u1);
#pragma unroll
        for (int q = 0; q < 4; q++) {
            float2 f0 = __half22float2(h0[q]);
            float2 f1 = __half22float2(h1[q]);
            a0[q * 2]     += f0.x;
            a0[q * 2 + 1] += f0.y;
            a1[q * 2]     += f1.x;
            a1[q * 2 + 1] += f1.y;
        }
    }
    if (e < end) {
        int s0 = __ldg(col + e);
        uint4 u0 = __ldg(reinterpret_cast<const uint4*>(X + (size_t)s0 * D + c));
        const __half2* h0 = reinterpret_cast<const __half2*>(&u0);
#pragma unroll
        for (int q = 0; q < 4; q++) {
            float2 f0 = __half22float2(h0[q]);
            a0[q * 2]     += f0.x;
            a0[q * 2 + 1] += f0.y;
        }
    }

    float4 r0, r1;
    r0.x = a0[0] + a1[0]; r0.y = a0[1] + a1[1];
    r0.z = a0[2] + a1[2]; r0.w = a0[3] + a1[3];
    r1.x = a0[4] + a1[4]; r1.y = a0[5] + a1[5];
    r1.z = a0[6] + a1[6]; r1.w = a0[7] + a1[7];
    float* dst = AGG + (size_t)node * D + c;
    *reinterpret_cast<float4*>(dst)     = r0;
    *reinterpret_cast<float4*>(dst + 4) = r1;
}

// ------------------------------- pooling -----------------------------------

__device__ __forceinline__ int lower_bound_dev(const int* __restrict__ a, int n, int v) {
    int lo = 0, hi = n;
    while (lo < hi) {
        int m = (lo + hi) >> 1;
        if (a[m] < v) lo = m + 1; else hi = m;
    }
    return lo;
}

__global__ void pool_kernel(const float* __restrict__ AGG, const float* __restrict__ innorm,
                            const float* __restrict__ b3, const int* __restrict__ gids,
                            float* __restrict__ out, int Nn) {
    int g = blockIdx.x;
    int lo = lower_bound_dev(gids, Nn, g);
    int hi = lower_bound_dev(gids, Nn, g + 1);
    int f = threadIdx.x & 63;
    int slot = threadIdx.x >> 6;
    float bf = b3[f];
    float sum = 0.f;
    for (int i = lo + slot; i < hi; i += 4)
        sum += fmaf(AGG[(size_t)i * 64 + f], innorm[i], bf);
    __shared__ float sh[256];
    sh[threadIdx.x] = sum;
    __syncthreads();
    if (slot == 0) {
        float tot = sh[f] + sh[64 + f] + sh[128 + f] + sh[192 + f];
        float cnt = (float)(hi - lo);
        out[g * 64 + f] = tot / fmaxf(cnt, 1.f);
    }
}

// ------------------------------- launch ------------------------------------

extern "C" void kernel_launch(void* const* d_in, const int* in_sizes, int n_in,
                              void* d_out, int out_size) {
    const float* emb = (const float*)d_in[0];
    const float* W1  = (const float*)d_in[1];
    const float* b1  = (const float*)d_in[2];
    const float* W2  = (const float*)d_in[3];
    const float* b2  = (const float*)d_in[4];
    const float* W3  = (const float*)d_in[5];
    const float* b3  = (const float*)d_in[6];
    const int*   src = (const int*)d_in[7];
    const int*   dst = (const int*)d_in[8];
    const int*   gid = (const int*)d_in[9];
    float* out = (float*)d_out;

    const int Nn = in_sizes[0] / 128;   // 100000
    const int E  = in_sizes[7];         // 1600000
    const int G  = out_size / 64;       // 64

    __half* X;
    float *AGG, *onrm, *inrm;
    int *indeg, *outdeg, *rowptr, *fillc, *colA, *bsums;
    cudaGetSymbolAddress((void**)&X,      g_X);
    cudaGetSymbolAddress((void**)&AGG,    g_AGG);
    cudaGetSymbolAddress((void**)&onrm,   g_outnorm);
    cudaGetSymbolAddress((void**)&inrm,   g_innorm);
    cudaGetSymbolAddress((void**)&indeg,  g_indeg);
    cudaGetSymbolAddress((void**)&outdeg, g_outdeg);
    cudaGetSymbolAddress((void**)&rowptr, g_rowptr);
    cudaGetSymbolAddress((void**)&fillc,  g_fill);
    cudaGetSymbolAddress((void**)&colA,   g_col);
    cudaGetSymbolAddress((void**)&bsums,  g_bsums);

    const int smem128 = 2 * (20480 + 2 * 128 * 80);  // 81920
    const int smem64  = 2 * (20480 + 2 * 64 * 80);   // 61440
    cudaFuncSetAttribute(gemm_mma_kernel<128, 128, 0>,
                         cudaFuncAttributeMaxDynamicSharedMemorySize, smem128);
    cudaFuncSetAttribute(gemm_mma_kernel<128, 64, 1>,
                         cudaFuncAttributeMaxDynamicSharedMemorySize, smem64);
    cudaFuncSetAttribute(gemm_mma_kernel<64, 64, 1>,
                         cudaFuncAttributeMaxDynamicSharedMemorySize, smem64);

    const int T = 256;
    const int gemm_grid = (Nn + 127) / 128;
    const int nb_scan = (Nn + SCAN_BS - 1) / SCAN_BS;

    // 1: zero degrees
    zero_int2_kernel<<<(Nn + T - 1) / T, T>>>(indeg, outdeg, Nn);
    // 2: degree histograms
    hist_kernel<<<(E + T - 1) / T, T>>>(src, dst, outdeg, indeg, E);
    // 3: norms (GEMM1 needs outnorm only)
    norm_kernel<<<(Nn + T - 1) / T, T>>>(outdeg, indeg, onrm, inrm, Nn);
    // 4: layer-1 GEMM  (ncu capture slot — profile lands here)
    gemm_mma_kernel<128, 128, 0><<<gemm_grid, T, smem128>>>(emb, W1, nullptr, onrm, inrm, X, Nn);
    // 5-7: CSR build (independent of GEMM1 output)
    scanA_kernel<<<nb_scan, SCAN_BS>>>(indeg, rowptr, bsums, Nn);
    scanBC_kernel<<<(Nn + 255) / 256, 256>>>(rowptr, fillc, bsums, nb_scan, Nn, E);
    fill_kernel<<<(E + T - 1) / T, T>>>(src, dst, fillc, colA, E);
    // 8: gather layer 1
    gather_kernel<128><<<(Nn * 16 + T - 1) / T, T>>>(X, rowptr, colA, AGG, Nn);

    // Layer 2
    gemm_mma_kernel<128, 64, 1><<<gemm_grid, T, smem64>>>(AGG, W2, b1, onrm, inrm, X, Nn);
    gather_kernel<64><<<(Nn * 8 + T - 1) / T, T>>>(X, rowptr, colA, AGG, Nn);

    // Layer 3
    gemm_mma_kernel<64, 64, 1><<<gemm_grid, T, smem64>>>(AGG, W3, b2, onrm, inrm, X, Nn);
    gather_kernel<64><<<(Nn * 8 + T - 1) / T, T>>>(X, rowptr, colA, AGG, Nn);

    // Pool
    pool_kernel<<<G, T>>>(AGG, inrm, b3, gid, out, Nn);
}

// round 10
// speedup vs baseline: 1.0328x; 1.0328x over previous
#include <cuda_runtime.h>
#include <cuda_bf16.h>
#include <cuda_fp16.h>
#include <cstdint>

// ---------------------------------------------------------------------------
// GCN: 3x (pointwise -> bf16x3 mma.sync GEMM -> CSR gather-sum) + mean pool
// R8->R9 (resubmit; prior run hit infra failure): GEMMs use 512-thread CTAs
// (4x4 warp grid) -> lower regs/thread, 2x occupancy. W pre-split to bf16
// hi/lo in global (transposed) by a prep kernel fused with degree zeroing.
// ---------------------------------------------------------------------------

#define MAX_NODES 100000
#define MAX_EDGES 1600000
#define MAX_FEATS 128
#define SCAN_BS 512

__device__ __half g_X[MAX_NODES * MAX_FEATS];   // GEMM outputs, fp16 (gather input)
__device__ float  g_AGG[MAX_NODES * MAX_FEATS]; // gathered sums, fp32
__device__ float  g_outnorm[MAX_NODES];
__device__ float  g_innorm[MAX_NODES];
__device__ int    g_indeg[MAX_NODES];
__device__ int    g_outdeg[MAX_NODES];
__device__ int    g_rowptr[MAX_NODES + 1];
__device__ int    g_fill[MAX_NODES];
__device__ int    g_col[MAX_EDGES];
__device__ int    g_bsums[(MAX_NODES + SCAN_BS - 1) / SCAN_BS];
// Pre-split transposed weights (n-major, K contiguous): W1 | W2 | W3
__device__ __align__(16) __nv_bfloat16 g_Wh[28672];
__device__ __align__(16) __nv_bfloat16 g_Wl[28672];
#define W2_OFF 16384
#define W3_OFF 24576

// ----------------------------- helpers -------------------------------------

__device__ __forceinline__ uint32_t smem_u32(const void* p) {
    uint32_t a;
    asm("{ .reg .u64 t; cvta.to.shared.u64 t, %1; cvt.u32.u64 %0, t; }" : "=r"(a) : "l"(p));
    return a;
}

__device__ __forceinline__ void ldsm_x4(uint32_t* r, uint32_t addr) {
    asm volatile("ldmatrix.sync.aligned.m8n8.x4.shared.b16 {%0,%1,%2,%3}, [%4];"
                 : "=r"(r[0]), "=r"(r[1]), "=r"(r[2]), "=r"(r[3]) : "r"(addr));
}

__device__ __forceinline__ void mma_bf16(float* d, const uint32_t* a, const uint32_t* b) {
    asm volatile("mma.sync.aligned.m16n8k16.row.col.f32.bf16.bf16.f32 "
                 "{%0,%1,%2,%3}, {%4,%5,%6,%7}, {%8,%9}, {%0,%1,%2,%3};"
                 : "+f"(d[0]), "+f"(d[1]), "+f"(d[2]), "+f"(d[3])
                 : "r"(a[0]), "r"(a[1]), "r"(a[2]), "r"(a[3]), "r"(b[0]), "r"(b[1]));
}

__device__ __forceinline__ void split2(float x, float y, uint32_t& hi, uint32_t& lo) {
    __nv_bfloat162 h = __floats2bfloat162_rn(x, y);
    float rx = x - __bfloat162float(h.x);
    float ry = y - __bfloat162float(h.y);
    __nv_bfloat162 l = __floats2bfloat162_rn(rx, ry);
    hi = reinterpret_cast<uint32_t&>(h);
    lo = reinterpret_cast<uint32_t&>(l);
}

// --------------------- prep: zero degrees + split W ------------------------

__global__ void prep_kernel(const float* __restrict__ W1, const float* __restrict__ W2,
                            const float* __restrict__ W3,
                            __nv_bfloat16* __restrict__ Wh, __nv_bfloat16* __restrict__ Wl,
                            int* __restrict__ indeg, int* __restrict__ outdeg, int n) {
    int i = blockIdx.x * blockDim.x + threadIdx.x;
    if (i < n) { indeg[i] = 0; outdeg[i] = 0; }
    // W1 [K=128 x N=128] -> transposed [n][k]
    if (i < 128 * 128) {
        int nn = i >> 7, k = i & 127;
        float w = W1[k * 128 + nn];
        __nv_bfloat16 h = __float2bfloat16_rn(w);
        Wh[i] = h;
        Wl[i] = __float2bfloat16_rn(w - __bfloat162float(h));
    }
    // W2 [K=128 x N=64]
    if (i < 64 * 128) {
        int nn = i >> 7, k = i & 127;
        float w = W2[k * 64 + nn];
        __nv_bfloat16 h = __float2bfloat16_rn(w);
        Wh[W2_OFF + i] = h;
        Wl[W2_OFF + i] = __float2bfloat16_rn(w - __bfloat162float(h));
    }
    // W3 [K=64 x N=64]
    if (i < 64 * 64) {
        int nn = i >> 6, k = i & 63;
        float w = W3[k * 64 + nn];
        __nv_bfloat16 h = __float2bfloat16_rn(w);
        Wh[W3_OFF + i] = h;
        Wl[W3_OFF + i] = __float2bfloat16_rn(w - __bfloat162float(h));
    }
}

// --------------------------- CSR construction ------------------------------

__global__ void hist_kernel(const int* __restrict__ src, const int* __restrict__ dst,
                            int* __restrict__ outdeg, int* __restrict__ indeg, int E) {
    int i = blockIdx.x * blockDim.x + threadIdx.x;
    if (i < E) {
        atomicAdd(outdeg + src[i], 1);
        atomicAdd(indeg + dst[i], 1);
    }
}

__global__ void norm_kernel(const int* __restrict__ od, const int* __restrict__ id,
                            float* __restrict__ onrm, float* __restrict__ inrm, int n) {
    int i = blockIdx.x * blockDim.x + threadIdx.x;
    if (i < n) {
        onrm[i] = rsqrtf(fmaxf((float)od[i], 1.0f));
        inrm[i] = rsqrtf(fmaxf((float)id[i], 1.0f));
    }
}

__global__ void scanA_kernel(const int* __restrict__ deg, int* __restrict__ rowptr,
                             int* __restrict__ bsums, int n) {
    __shared__ int sh[SCAN_BS];
    int t = threadIdx.x;
    int i = blockIdx.x * SCAN_BS + t;
    int v = (i < n) ? deg[i] : 0;
    sh[t] = v;
    __syncthreads();
#pragma unroll
    for (int off = 1; off < SCAN_BS; off <<= 1) {
        int x = (t >= off) ? sh[t - off] : 0;
        __syncthreads();
        sh[t] += x;
        __syncthreads();
    }
    if (i < n) rowptr[i] = sh[t] - v;
    if (t == SCAN_BS - 1) bsums[blockIdx.x] = sh[t];
}

__global__ void scanBC_kernel(int* __restrict__ rowptr, int* __restrict__ fill,
                              const int* __restrict__ bsums, int nb, int n, int E) {
    __shared__ int pref[256];
    int t = threadIdx.x;
    int v = (t < nb) ? bsums[t] : 0;
    pref[t] = v;
    __syncthreads();
#pragma unroll
    for (int off = 1; off < 256; off <<= 1) {
        int x = (t >= off) ? pref[t - off] : 0;
        __syncthreads();
        pref[t] += x;
        __syncthreads();
    }
    int i = blockIdx.x * blockDim.x + t;
    if (i < n) {
        int b = i / SCAN_BS;
        int excl = pref[b] - bsums[b];
        int r = rowptr[i] + excl;
        rowptr[i] = r;
        fill[i] = r;
    }
    if (i == 0) rowptr[n] = E;
}

__global__ void fill_kernel(const int* __restrict__ src, const int* __restrict__ dst,
                            int* __restrict__ fill, int* __restrict__ col, int E) {
    int i = blockIdx.x * blockDim.x + threadIdx.x;
    if (i < E) {
        int p = atomicAdd(fill + dst[i], 1);
        col[p] = src[i];
    }
}

// --------------------------- bf16x3 GEMM -----------------------------------
// X[M,N] (fp16) = f(A[M,K]) @ W[K,N], CTA tile 128 x N, 512 threads (4x4 warps).
// W comes pre-split/transposed (bf16 hi/lo, n-major, K contiguous).
// MODE 0: f(a)[r,k] = a[r,k] * outnorm[r]
// MODE 1: f(a)[r,k] = relu(a[r,k]*innorm[r] + bprev[k]) * outnorm[r]
// bf16x3: D = Ah@Bh + Ah@Bl + Al@Bh, fp32 accum (mma.sync m16n8k16).

template<int K, int N, int MODE>
__global__ __launch_bounds__(512)
void gemm_mma_kernel(const float* __restrict__ A,
                     const __nv_bfloat16* __restrict__ Wh,
                     const __nv_bfloat16* __restrict__ Wl,
                     const float* __restrict__ bprev,
                     const float* __restrict__ outnorm, const float* __restrict__ innorm,
                     __half* __restrict__ X, int M) {
    constexpr int BK = 32;
    constexpr int NCHUNK = K / BK;
    constexpr int WN = N / 4;        // warp tile cols (4x4 warp grid)
    constexpr int NT = WN / 8;       // 4 for N=128, 2 for N=64
    constexpr int MT = 2;
    constexpr int P = 40;            // smem pitch in bf16 (80B, LDSM-clean)
    constexpr int A_HI = 0;
    constexpr int A_LO = 128 * P * 2;            // 10240
    constexpr int W_HI = 2 * A_LO;               // 20480
    constexpr int W_SZ = N * P * 2;
    constexpr int W_LO = W_HI + W_SZ;
    constexpr int BUFS = W_LO + W_SZ;
    constexpr int WGRP = N * 4;                  // groups of 8 k-elems per chunk

    extern __shared__ char smem[];
    const uint32_t sb = smem_u32(smem);
    const int tid = threadIdx.x;
    const int lane = tid & 31;
    const int wid = tid >> 5;        // 0..15
    const int warp_m = wid >> 2;     // 0..3
    const int warp_n = wid & 3;      // 0..3
    const int row0 = blockIdx.x * 128;

    // A-load mapping: 4 threads per row, each covers 8 cols (2 float4)
    const int arow = tid & 127;
    const int aq = tid >> 7;         // 0..3 -> cols [aq*8, aq*8+8)
    const int grow = row0 + arow;
    const bool valid = grow < M;
    const float on  = valid ? outnorm[grow] : 0.f;
    const float inn = (MODE == 1 && valid) ? innorm[grow] : 0.f;

    // ldmatrix per-lane bases
    const int a_r = warp_m * 32 + ((lane >> 3) & 1) * 8 + (lane & 7);
    const int a_k = (lane >> 4) * 8;
    const int b_n = warp_n * WN + (lane >> 4) * 8 + (lane & 7);
    const int b_k = ((lane >> 3) & 1) * 8;

    // W-load mapping: group g covers (n = g/4, k8 = g%4)
    const int wg_n = tid >> 2;
    const int wg_k8 = tid & 3;
    const bool wg_ok = tid < WGRP;   // always true for N=128; half for N=64

    float acc[MT][NT][4];
#pragma unroll
    for (int i = 0; i < MT; i++)
#pragma unroll
        for (int j = 0; j < NT; j++)
#pragma unroll
            for (int q = 0; q < 4; q++) acc[i][j][q] = 0.f;

    float4 av[2];
    uint4 whv, wlv;

    auto load_g = [&](int c) {
        const int kc = c * BK;
#pragma unroll
        for (int q = 0; q < 2; q++) {
            const int col = aq * 8 + q * 4;
            float4 v = make_float4(0.f, 0.f, 0.f, 0.f);
            if (valid) {
                v = *reinterpret_cast<const float4*>(A + (size_t)grow * K + kc + col);
                if (MODE == 0) {
                    v.x *= on; v.y *= on; v.z *= on; v.w *= on;
                } else {
                    float4 b = *reinterpret_cast<const float4*>(bprev + kc + col);
                    v.x = fmaxf(fmaf(v.x, inn, b.x), 0.f) * on;
                    v.y = fmaxf(fmaf(v.y, inn, b.y), 0.f) * on;
                    v.z = fmaxf(fmaf(v.z, inn, b.z), 0.f) * on;
                    v.w = fmaxf(fmaf(v.w, inn, b.w), 0.f) * on;
                }
            }
            av[q] = v;
        }
        if (wg_ok) {
            const size_t woff = (size_t)wg_n * K + kc + wg_k8 * 8;
            whv = *reinterpret_cast<const uint4*>(Wh + woff);
            wlv = *reinterpret_cast<const uint4*>(Wl + woff);
        }
    };

    auto store_s = [&](int buf) {
        char* base = smem + buf * BUFS;
#pragma unroll
        for (int q = 0; q < 2; q++) {
            const int col = aq * 8 + q * 4;
            uint32_t h01, l01, h23, l23;
            split2(av[q].x, av[q].y, h01, l01);
            split2(av[q].z, av[q].w, h23, l23);
            const uint32_t off = (uint32_t)arow * (P * 2) + col * 2;
            *reinterpret_cast<uint2*>(base + A_HI + off) = make_uint2(h01, h23);
            *reinterpret_cast<uint2*>(base + A_LO + off) = make_uint2(l01, l23);
        }
        if (wg_ok) {
            const uint32_t off = (uint32_t)wg_n * (P * 2) + wg_k8 * 16;
            *reinterpret_cast<uint4*>(base + W_HI + off) = whv;
            *reinterpret_cast<uint4*>(base + W_LO + off) = wlv;
        }
    };

    auto compute = [&](int buf) {
        const uint32_t ab = sb + buf * BUFS;
#pragma unroll
        for (int ks = 0; ks < 2; ks++) {
            uint32_t ah[MT][4], al[MT][4];
#pragma unroll
            for (int i = 0; i < MT; i++) {
                const uint32_t addr = ab + A_HI +
                    (uint32_t)(a_r + i * 16) * (P * 2) + (a_k + ks * 16) * 2;
                ldsm_x4(ah[i], addr);
                ldsm_x4(al[i], addr + A_LO);
            }
#pragma unroll
            for (int p = 0; p < NT / 2; p++) {
                uint32_t bh[4], bl[4];
                const uint32_t baddr = ab + W_HI +
                    (uint32_t)(b_n + p * 16) * (P * 2) + (b_k + ks * 16) * 2;
                ldsm_x4(bh, baddr);
                ldsm_x4(bl, baddr + W_SZ);
#pragma unroll
                for (int i = 0; i < MT; i++)
#pragma unroll
                    for (int jj = 0; jj < 2; jj++) {
                        float* d = acc[i][p * 2 + jj];
                        mma_bf16(d, ah[i], bh + jj * 2);
                        mma_bf16(d, ah[i], bl + jj * 2);
                        mma_bf16(d, al[i], bh + jj * 2);
                    }
            }
        }
    };

    load_g(0);
    store_s(0);
    __syncthreads();

    for (int c = 0; c < NCHUNK; c++) {
        if (c + 1 < NCHUNK) load_g(c + 1);
        compute(c & 1);
        if (c + 1 < NCHUNK) store_s((c + 1) & 1);
        __syncthreads();
    }

    // epilogue: fp32 acc -> fp16 X
#pragma unroll
    for (int i = 0; i < MT; i++) {
        const int r0 = row0 + warp_m * 32 + i * 16 + (lane >> 2);
#pragma unroll
        for (int j = 0; j < NT; j++) {
            const int n0 = warp_n * WN + j * 8 + (lane & 3) * 2;
            if (r0 < M)
                *reinterpret_cast<__half2*>(X + (size_t)r0 * N + n0) =
                    __floats2half2_rn(acc[i][j][0], acc[i][j][1]);
            if (r0 + 8 < M)
                *reinterpret_cast<__half2*>(X + (size_t)(r0 + 8) * N + n0) =
                    __floats2half2_rn(acc[i][j][2], acc[i][j][3]);
        }
    }
}

// ------------------------------ CSR gather ---------------------------------
// AGG[n] (fp32) = sum over e in [rowptr[n], rowptr[n+1]) of X[col[e]] (fp16)
// D/8 lanes per node; each lane loads 16B = 8 halves per edge; 2-edge unroll.

template<int D>
__global__ __launch_bounds__(256)
void gather_kernel(const __half* __restrict__ X, const int* __restrict__ rowptr,
                   const int* __restrict__ col, float* __restrict__ AGG, int Nn) {
    constexpr int LPN = D / 8;   // 16 for D=128, 8 for D=64
    int t = blockIdx.x * blockDim.x + threadIdx.x;
    int node = t / LPN;
    if (node >= Nn) return;
    int c = (t % LPN) * 8;
    int beg = __ldg(rowptr + node);
    int end = __ldg(rowptr + node + 1);

    float a0[8], a1[8];
#pragma unroll
    for (int q = 0; q < 8; q++) { a0[q] = 0.f; a1[q] = 0.f; }

    int e = beg;
    for (; e + 1 < end; e += 2) {
        int s0 = __ldg(col + e);
        int s1 = __ldg(col + e + 1);
        uint4 u0 = __ldg(reinterpret_cast<const uint4*>(X + (size_t)s0 * D + c));
        uint4 u1 = __ldg(reinterpret_cast<const uint4*>(X + (size_t)s1 * D + c));
        const __half2* h0 = reinterpret_cast<const __half2*>(&u0);
        const __half2* h1 = reinterpret_cast<const __half2*>(&u1);
#pragma unroll
        for (int q = 0; q < 4; q++) {
            float2 f0 = __half22float2(h0[q]);
            float2 f1 = __half22float2(h1[q]);
            a0[q * 2]     += f0.x;
            a0[q * 2 + 1] += f0.y;
            a1[q * 2]     += f1.x;
            a1[q * 2 + 1] += f1.y;
        }
    }
    if (e < end) {
        int s0 = __ldg(col + e);
        uint4 u0 = __ldg(reinterpret_cast<const uint4*>(X + (size_t)s0 * D + c));
        const __half2* h0 = reinterpret_cast<const __half2*>(&u0);
#pragma unroll
        for (int q = 0; q < 4; q++) {
            float2 f0 = __half22float2(h0[q]);
            a0[q * 2]     += f0.x;
            a0[q * 2 + 1] += f0.y;
        }
    }

    float4 r0, r1;
    r0.x = a0[0] + a1[0]; r0.y = a0[1] + a1[1];
    r0.z = a0[2] + a1[2]; r0.w = a0[3] + a1[3];
    r1.x = a0[4] + a1[4]; r1.y = a0[5] + a1[5];
    r1.z = a0[6] + a1[6]; r1.w = a0[7] + a1[7];
    float* dst = AGG + (size_t)node * D + c;
    *reinterpret_cast<float4*>(dst)     = r0;
    *reinterpret_cast<float4*>(dst + 4) = r1;
}

// ------------------------------- pooling -----------------------------------

__device__ __forceinline__ int lower_bound_dev(const int* __restrict__ a, int n, int v) {
    int lo = 0, hi = n;
    while (lo < hi) {
        int m = (lo + hi) >> 1;
        if (a[m] < v) lo = m + 1; else hi = m;
    }
    return lo;
}

__global__ void pool_kernel(const float* __restrict__ AGG, const float* __restrict__ innorm,
                            const float* __restrict__ b3, const int* __restrict__ gids,
                            float* __restrict__ out, int Nn) {
    int g = blockIdx.x;
    int lo = lower_bound_dev(gids, Nn, g);
    int hi = lower_bound_dev(gids, Nn, g + 1);
    int f = threadIdx.x & 63;
    int slot = threadIdx.x >> 6;
    float bf = b3[f];
    float sum = 0.f;
    for (int i = lo + slot; i < hi; i += 4)
        sum += fmaf(AGG[(size_t)i * 64 + f], innorm[i], bf);
    __shared__ float sh[256];
    sh[threadIdx.x] = sum;
    __syncthreads();
    if (slot == 0) {
        float tot = sh[f] + sh[64 + f] + sh[128 + f] + sh[192 + f];
        float cnt = (float)(hi - lo);
        out[g * 64 + f] = tot / fmaxf(cnt, 1.f);
    }
}

// ------------------------------- launch ------------------------------------

extern "C" void kernel_launch(void* const* d_in, const int* in_sizes, int n_in,
                              void* d_out, int out_size) {
    const float* emb = (const float*)d_in[0];
    const float* W1  = (const float*)d_in[1];
    const float* b1  = (const float*)d_in[2];
    const float* W2  = (const float*)d_in[3];
    const float* b2  = (const float*)d_in[4];
    const float* W3  = (const float*)d_in[5];
    const float* b3  = (const float*)d_in[6];
    const int*   src = (const int*)d_in[7];
    const int*   dst = (const int*)d_in[8];
    const int*   gid = (const int*)d_in[9];
    float* out = (float*)d_out;

    const int Nn = in_sizes[0] / 128;   // 100000
    const int E  = in_sizes[7];         // 1600000
    const int G  = out_size / 64;       // 64

    __half* X;
    float *AGG, *onrm, *inrm;
    int *indeg, *outdeg, *rowptr, *fillc, *colA, *bsums;
    __nv_bfloat16 *Wh, *Wl;
    cudaGetSymbolAddress((void**)&X,      g_X);
    cudaGetSymbolAddress((void**)&AGG,    g_AGG);
    cudaGetSymbolAddress((void**)&onrm,   g_outnorm);
    cudaGetSymbolAddress((void**)&inrm,   g_innorm);
    cudaGetSymbolAddress((void**)&indeg,  g_indeg);
    cudaGetSymbolAddress((void**)&outdeg, g_outdeg);
    cudaGetSymbolAddress((void**)&rowptr, g_rowptr);
    cudaGetSymbolAddress((void**)&fillc,  g_fill);
    cudaGetSymbolAddress((void**)&colA,   g_col);
    cudaGetSymbolAddress((void**)&bsums,  g_bsums);
    cudaGetSymbolAddress((void**)&Wh,     g_Wh);
    cudaGetSymbolAddress((void**)&Wl,     g_Wl);

    const int smem128 = 2 * (20480 + 2 * 128 * 80);  // 81920
    const int smem64  = 2 * (20480 + 2 * 64 * 80);   // 61440
    cudaFuncSetAttribute(gemm_mma_kernel<128, 128, 0>,
                         cudaFuncAttributeMaxDynamicSharedMemorySize, smem128);
    cudaFuncSetAttribute(gemm_mma_kernel<128, 64, 1>,
                         cudaFuncAttributeMaxDynamicSharedMemorySize, smem64);
    cudaFuncSetAttribute(gemm_mma_kernel<64, 64, 1>,
                         cudaFuncAttributeMaxDynamicSharedMemorySize, smem64);

    const int T = 256;
    const int gemm_grid = (Nn + 127) / 128;
    const int nb_scan = (Nn + SCAN_BS - 1) / SCAN_BS;

    // 1: zero degrees + pre-split W (fused)
    prep_kernel<<<(Nn + T - 1) / T, T>>>(W1, W2, W3, Wh, Wl, indeg, outdeg, Nn);
    // 2: degree histograms
    hist_kernel<<<(E + T - 1) / T, T>>>(src, dst, outdeg, indeg, E);
    // 3: norms
    norm_kernel<<<(Nn + T - 1) / T, T>>>(outdeg, indeg, onrm, inrm, Nn);
    // 4: layer-1 GEMM  (ncu capture slot)
    gemm_mma_kernel<128, 128, 0><<<gemm_grid, 512, smem128>>>(emb, Wh, Wl, nullptr,
                                                              onrm, inrm, X, Nn);
    // 5-7: CSR build
    scanA_kernel<<<nb_scan, SCAN_BS>>>(indeg, rowptr, bsums, Nn);
    scanBC_kernel<<<(Nn + 255) / 256, 256>>>(rowptr, fillc, bsums, nb_scan, Nn, E);
    fill_kernel<<<(E + T - 1) / T, T>>>(src, dst, fillc, colA, E);
    // 8: gather layer 1
    gather_kernel<128><<<(Nn * 16 + T - 1) / T, T>>>(X, rowptr, colA, AGG, Nn);

    // Layer 2
    gemm_mma_kernel<128, 64, 1><<<gemm_grid, 512, smem64>>>(AGG, Wh + W2_OFF, Wl + W2_OFF,
                                                            b1, onrm, inrm, X, Nn);
    gather_kernel<64><<<(Nn * 8 + T - 1) / T, T>>>(X, rowptr, colA, AGG, Nn);

    // Layer 3
    gemm_mma_kernel<64, 64, 1><<<gemm_grid, 512, smem64>>>(AGG, Wh + W3_OFF, Wl + W3_OFF,
                                                           b2, onrm, inrm, X, Nn);
    gather_kernel<64><<<(Nn * 8 + T - 1) / T, T>>>(X, rowptr, colA, AGG, Nn);

    // Pool
    pool_kernel<<<G, T>>>(AGG, inrm, b3, gid, out, Nn);
}

// round 12
// speedup vs baseline: 1.1361x; 1.1000x over previous
#include <cuda_runtime.h>
#include <cuda_bf16.h>
#include <cuda_fp16.h>
#include <cstdint>

// ---------------------------------------------------------------------------
// GCN: 3x (pointwise -> bf16x3 mma.sync GEMM -> CSR gather-sum) + mean pool
// R11 resubmit (two infra failures, source unvalidated): GEMM tiles 64xN with
// 256 threads, __launch_bounds__(256,3) -> 3 independent CTAs/SM to hide DRAM
// latency (R10: 1 CTA/SM, issue=16%). AGG stored fp16 (fp16->bf16x2 split is
// exact), halving gather-write + GEMM2/3 A-read + pool traffic.
// ---------------------------------------------------------------------------

#define MAX_NODES 100000
#define MAX_EDGES 1600000
#define MAX_FEATS 128
#define SCAN_BS 512

__device__ __half g_X[MAX_NODES * MAX_FEATS];   // GEMM outputs, fp16
__device__ __half g_AGG[MAX_NODES * MAX_FEATS]; // gathered sums, fp16
__device__ float  g_outnorm[MAX_NODES];
__device__ float  g_innorm[MAX_NODES];
__device__ int    g_indeg[MAX_NODES];
__device__ int    g_outdeg[MAX_NODES];
__device__ int    g_rowptr[MAX_NODES + 1];
__device__ int    g_fill[MAX_NODES];
__device__ int    g_col[MAX_EDGES];
__device__ int    g_bsums[(MAX_NODES + SCAN_BS - 1) / SCAN_BS];
// Pre-split transposed weights (n-major, K contiguous): W1 | W2 | W3
__device__ __align__(16) __nv_bfloat16 g_Wh[28672];
__device__ __align__(16) __nv_bfloat16 g_Wl[28672];
#define W2_OFF 16384
#define W3_OFF 24576

// ----------------------------- helpers -------------------------------------

__device__ __forceinline__ uint32_t smem_u32(const void* p) {
    uint32_t a;
    asm("{ .reg .u64 t; cvta.to.shared.u64 t, %1; cvt.u32.u64 %0, t; }" : "=r"(a) : "l"(p));
    return a;
}

__device__ __forceinline__ void ldsm_x4(uint32_t* r, uint32_t addr) {
    asm volatile("ldmatrix.sync.aligned.m8n8.x4.shared.b16 {%0,%1,%2,%3}, [%4];"
                 : "=r"(r[0]), "=r"(r[1]), "=r"(r[2]), "=r"(r[3]) : "r"(addr));
}

__device__ __forceinline__ void mma_bf16(float* d, const uint32_t* a, const uint32_t* b) {
    asm volatile("mma.sync.aligned.m16n8k16.row.col.f32.bf16.bf16.f32 "
                 "{%0,%1,%2,%3}, {%4,%5,%6,%7}, {%8,%9}, {%0,%1,%2,%3};"
                 : "+f"(d[0]), "+f"(d[1]), "+f"(d[2]), "+f"(d[3])
                 : "r"(a[0]), "r"(a[1]), "r"(a[2]), "r"(a[3]), "r"(b[0]), "r"(b[1]));
}

__device__ __forceinline__ void split2(float x, float y, uint32_t& hi, uint32_t& lo) {
    __nv_bfloat162 h = __floats2bfloat162_rn(x, y);
    float rx = x - __bfloat162float(h.x);
    float ry = y - __bfloat162float(h.y);
    __nv_bfloat162 l = __floats2bfloat162_rn(rx, ry);
    hi = reinterpret_cast<uint32_t&>(h);
    lo = reinterpret_cast<uint32_t&>(l);
}

// --------------------- prep: zero degrees + split W ------------------------

__global__ void prep_kernel(const float* __restrict__ W1, const float* __restrict__ W2,
                            const float* __restrict__ W3,
                            __nv_bfloat16* __restrict__ Wh, __nv_bfloat16* __restrict__ Wl,
                            int* __restrict__ indeg, int* __restrict__ outdeg, int n) {
    int i = blockIdx.x * blockDim.x + threadIdx.x;
    if (i < n) { indeg[i] = 0; outdeg[i] = 0; }
    if (i < 128 * 128) {
        int nn = i >> 7, k = i & 127;
        float w = W1[k * 128 + nn];
        __nv_bfloat16 h = __float2bfloat16_rn(w);
        Wh[i] = h;
        Wl[i] = __float2bfloat16_rn(w - __bfloat162float(h));
    }
    if (i < 64 * 128) {
        int nn = i >> 7, k = i & 127;
        float w = W2[k * 64 + nn];
        __nv_bfloat16 h = __float2bfloat16_rn(w);
        Wh[W2_OFF + i] = h;
        Wl[W2_OFF + i] = __float2bfloat16_rn(w - __bfloat162float(h));
    }
    if (i < 64 * 64) {
        int nn = i >> 6, k = i & 63;
        float w = W3[k * 64 + nn];
        __nv_bfloat16 h = __float2bfloat16_rn(w);
        Wh[W3_OFF + i] = h;
        Wl[W3_OFF + i] = __float2bfloat16_rn(w - __bfloat162float(h));
    }
}

// --------------------------- CSR construction ------------------------------

__global__ void hist_kernel(const int* __restrict__ src, const int* __restrict__ dst,
                            int* __restrict__ outdeg, int* __restrict__ indeg, int E) {
    int i = blockIdx.x * blockDim.x + threadIdx.x;
    if (i < E) {
        atomicAdd(outdeg + src[i], 1);
        atomicAdd(indeg + dst[i], 1);
    }
}

__global__ void norm_kernel(const int* __restrict__ od, const int* __restrict__ id,
                            float* __restrict__ onrm, float* __restrict__ inrm, int n) {
    int i = blockIdx.x * blockDim.x + threadIdx.x;
    if (i < n) {
        onrm[i] = rsqrtf(fmaxf((float)od[i], 1.0f));
        inrm[i] = rsqrtf(fmaxf((float)id[i], 1.0f));
    }
}

__global__ void scanA_kernel(const int* __restrict__ deg, int* __restrict__ rowptr,
                             int* __restrict__ bsums, int n) {
    __shared__ int sh[SCAN_BS];
    int t = threadIdx.x;
    int i = blockIdx.x * SCAN_BS + t;
    int v = (i < n) ? deg[i] : 0;
    sh[t] = v;
    __syncthreads();
#pragma unroll
    for (int off = 1; off < SCAN_BS; off <<= 1) {
        int x = (t >= off) ? sh[t - off] : 0;
        __syncthreads();
        sh[t] += x;
        __syncthreads();
    }
    if (i < n) rowptr[i] = sh[t] - v;
    if (t == SCAN_BS - 1) bsums[blockIdx.x] = sh[t];
}

__global__ void scanBC_kernel(int* __restrict__ rowptr, int* __restrict__ fill,
                              const int* __restrict__ bsums, int nb, int n, int E) {
    __shared__ int pref[256];
    int t = threadIdx.x;
    int v = (t < nb) ? bsums[t] : 0;
    pref[t] = v;
    __syncthreads();
#pragma unroll
    for (int off = 1; off < 256; off <<= 1) {
        int x = (t >= off) ? pref[t - off] : 0;
        __syncthreads();
        pref[t] += x;
        __syncthreads();
    }
    int i = blockIdx.x * blockDim.x + t;
    if (i < n) {
        int b = i / SCAN_BS;
        int excl = pref[b] - bsums[b];
        int r = rowptr[i] + excl;
        rowptr[i] = r;
        fill[i] = r;
    }
    if (i == 0) rowptr[n] = E;
}

__global__ void fill_kernel(const int* __restrict__ src, const int* __restrict__ dst,
                            int* __restrict__ fill, int* __restrict__ col, int E) {
    int i = blockIdx.x * blockDim.x + threadIdx.x;
    if (i < E) {
        int p = atomicAdd(fill + dst[i], 1);
        col[p] = src[i];
    }
}

// --------------------------- bf16x3 GEMM -----------------------------------
// X[M,N] (fp16) = f(A[M,K]) @ W[K,N], CTA tile 64 x N, 256 threads (2x4 warps),
// 3 CTAs/SM for DRAM-latency overlap. W pre-split bf16 hi/lo (n-major).
// MODE 0: A fp32; f(a)[r,k] = a[r,k] * outnorm[r]
// MODE 1: A fp16; f(a)[r,k] = relu(a[r,k]*innorm[r] + bprev[k]) * outnorm[r]
// bf16x3: D = Ah@Bh + Ah@Bl + Al@Bh, fp32 accum (mma.sync m16n8k16).

template<int K, int N, int MODE>
__global__ __launch_bounds__(256, 3)
void gemm_mma_kernel(const void* __restrict__ Ain,
                     const __nv_bfloat16* __restrict__ Wh,
                     const __nv_bfloat16* __restrict__ Wl,
                     const float* __restrict__ bprev,
                     const float* __restrict__ outnorm, const float* __restrict__ innorm,
                     __half* __restrict__ X, int M) {
    constexpr int BK = 32;
    constexpr int NCHUNK = K / BK;
    constexpr int WN = N / 4;        // warp tile cols (2x4 warp grid)
    constexpr int NT = WN / 8;       // 4 for N=128, 2 for N=64
    constexpr int MT = 2;
    constexpr int P = 40;            // smem pitch in bf16 (80B, LDSM-clean)
    constexpr int A_HI = 0;
    constexpr int A_LO = 64 * P * 2;             // 5120
    constexpr int W_HI = 2 * A_LO;               // 10240
    constexpr int W_SZ = N * P * 2;
    constexpr int W_LO = W_HI + W_SZ;
    constexpr int BUFS = W_LO + W_SZ;
    constexpr int WCNT = (N == 128) ? 2 : 1;     // W uint4 groups per thread

    extern __shared__ char smem[];
    const uint32_t sb = smem_u32(smem);
    const int tid = threadIdx.x;
    const int lane = tid & 31;
    const int wid = tid >> 5;        // 0..7
    const int warp_m = wid >> 2;     // 0..1
    const int warp_n = wid & 3;      // 0..3
    const int row0 = blockIdx.x * 64;

    // A-load mapping: 4 threads per row, each covers 8 cols
    const int arow = tid & 63;
    const int aq = tid >> 6;         // 0..3 -> cols [aq*8, aq*8+8)
    const int col0 = aq * 8;
    const int grow = row0 + arow;
    const bool valid = grow < M;
    const float on  = valid ? outnorm[grow] : 0.f;
    const float inn = (MODE == 1 && valid) ? innorm[grow] : 0.f;

    // ldmatrix per-lane bases
    const int a_r = warp_m * 32 + ((lane >> 3) & 1) * 8 + (lane & 7);
    const int a_k = (lane >> 4) * 8;
    const int b_n = warp_n * WN + (lane >> 4) * 8 + (lane & 7);
    const int b_k = ((lane >> 3) & 1) * 8;

    float acc[MT][NT][4];
#pragma unroll
    for (int i = 0; i < MT; i++)
#pragma unroll
        for (int j = 0; j < NT; j++)
#pragma unroll
            for (int q = 0; q < 4; q++) acc[i][j][q] = 0.f;

    float a8[8];
    uint4 whv[WCNT], wlv[WCNT];

    auto load_g = [&](int c) {
        const int kc = c * BK;
        if (MODE == 0) {
            const float* Af = (const float*)Ain;
            float4 v0 = make_float4(0.f, 0.f, 0.f, 0.f);
            float4 v1 = make_float4(0.f, 0.f, 0.f, 0.f);
            if (valid) {
                v0 = *reinterpret_cast<const float4*>(Af + (size_t)grow * K + kc + col0);
                v1 = *reinterpret_cast<const float4*>(Af + (size_t)grow * K + kc + col0 + 4);
            }
            a8[0] = v0.x * on; a8[1] = v0.y * on; a8[2] = v0.z * on; a8[3] = v0.w * on;
            a8[4] = v1.x * on; a8[5] = v1.y * on; a8[6] = v1.z * on; a8[7] = v1.w * on;
        } else {
            const __half* Ah16 = (const __half*)Ain;
            uint4 u = make_uint4(0u, 0u, 0u, 0u);
            if (valid)
                u = *reinterpret_cast<const uint4*>(Ah16 + (size_t)grow * K + kc + col0);
            float4 b0 = *reinterpret_cast<const float4*>(bprev + kc + col0);
            float4 b1 = *reinterpret_cast<const float4*>(bprev + kc + col0 + 4);
            const __half2* hp = reinterpret_cast<const __half2*>(&u);
            float2 f0 = __half22float2(hp[0]);
            float2 f1 = __half22float2(hp[1]);
            float2 f2 = __half22float2(hp[2]);
            float2 f3 = __half22float2(hp[3]);
            a8[0] = fmaxf(fmaf(f0.x, inn, b0.x), 0.f) * on;
            a8[1] = fmaxf(fmaf(f0.y, inn, b0.y), 0.f) * on;
            a8[2] = fmaxf(fmaf(f1.x, inn, b0.z), 0.f) * on;
            a8[3] = fmaxf(fmaf(f1.y, inn, b0.w), 0.f) * on;
            a8[4] = fmaxf(fmaf(f2.x, inn, b1.x), 0.f) * on;
            a8[5] = fmaxf(fmaf(f2.y, inn, b1.y), 0.f) * on;
            a8[6] = fmaxf(fmaf(f3.x, inn, b1.z), 0.f) * on;
            a8[7] = fmaxf(fmaf(f3.y, inn, b1.w), 0.f) * on;
        }
#pragma unroll
        for (int w = 0; w < WCNT; w++) {
            const int g = tid + w * 256;
            const int wn = g >> 2, wk8 = g & 3;
            const size_t woff = (size_t)wn * K + kc + wk8 * 8;
            whv[w] = *reinterpret_cast<const uint4*>(Wh + woff);
            wlv[w] = *reinterpret_cast<const uint4*>(Wl + woff);
        }
    };

    auto store_s = [&](int buf) {
        char* base = smem + buf * BUFS;
        uint4 h4, l4;
        split2(a8[0], a8[1], h4.x, l4.x);
        split2(a8[2], a8[3], h4.y, l4.y);
        split2(a8[4], a8[5], h4.z, l4.z);
        split2(a8[6], a8[7], h4.w, l4.w);
        const uint32_t aoff = (uint32_t)arow * (P * 2) + col0 * 2;
        *reinterpret_cast<uint4*>(base + A_HI + aoff) = h4;
        *reinterpret_cast<uint4*>(base + A_LO + aoff) = l4;
#pragma unroll
        for (int w = 0; w < WCNT; w++) {
            const int g = tid + w * 256;
            const int wn = g >> 2, wk8 = g & 3;
            const uint32_t off = (uint32_t)wn * (P * 2) + wk8 * 16;
            *reinterpret_cast<uint4*>(base + W_HI + off) = whv[w];
            *reinterpret_cast<uint4*>(base + W_LO + off) = wlv[w];
        }
    };

    auto compute = [&](int buf) {
        const uint32_t ab = sb + buf * BUFS;
#pragma unroll
        for (int ks = 0; ks < 2; ks++) {
            uint32_t ah[MT][4], al[MT][4];
#pragma unroll
            for (int i = 0; i < MT; i++) {
                const uint32_t addr = ab + A_HI +
                    (uint32_t)(a_r + i * 16) * (P * 2) + (a_k + ks * 16) * 2;
                ldsm_x4(ah[i], addr);
                ldsm_x4(al[i], addr + A_LO);
            }
#pragma unroll
            for (int p = 0; p < NT / 2; p++) {
                uint32_t bh[4], bl[4];
                const uint32_t baddr = ab + W_HI +
                    (uint32_t)(b_n + p * 16) * (P * 2) + (b_k + ks * 16) * 2;
                ldsm_x4(bh, baddr);
                ldsm_x4(bl, baddr + W_SZ);
#pragma unroll
                for (int i = 0; i < MT; i++)
#pragma unroll
                    for (int jj = 0; jj < 2; jj++) {
                        float* d = acc[i][p * 2 + jj];
                        mma_bf16(d, ah[i], bh + jj * 2);
                        mma_bf16(d, ah[i], bl + jj * 2);
                        mma_bf16(d, al[i], bh + jj * 2);
                    }
            }
        }
    };

    load_g(0);
    store_s(0);
    __syncthreads();

    for (int c = 0; c < NCHUNK; c++) {
        if (c + 1 < NCHUNK) load_g(c + 1);
        compute(c & 1);
        if (c + 1 < NCHUNK) store_s((c + 1) & 1);
        __syncthreads();
    }

    // epilogue: fp32 acc -> fp16 X
#pragma unroll
    for (int i = 0; i < MT; i++) {
        const int r0 = row0 + warp_m * 32 + i * 16 + (lane >> 2);
#pragma unroll
        for (int j = 0; j < NT; j++) {
            const int n0 = warp_n * WN + j * 8 + (lane & 3) * 2;
            if (r0 < M)
                *reinterpret_cast<__half2*>(X + (size_t)r0 * N + n0) =
                    __floats2half2_rn(acc[i][j][0], acc[i][j][1]);
            if (r0 + 8 < M)
                *reinterpret_cast<__half2*>(X + (size_t)(r0 + 8) * N + n0) =
                    __floats2half2_rn(acc[i][j][2], acc[i][j][3]);
        }
    }
}

// ------------------------------ CSR gather ---------------------------------
// AGG[n] (fp16) = sum over e in [rowptr[n], rowptr[n+1]) of X[col[e]] (fp16)
// fp32 accumulation in registers; D/8 lanes per node; 2-edge unroll.

template<int D>
__global__ __launch_bounds__(256)
void gather_kernel(const __half* __restrict__ X, const int* __restrict__ rowptr,
                   const int* __restrict__ col, __half* __restrict__ AGG, int Nn) {
    constexpr int LPN = D / 8;   // 16 for D=128, 8 for D=64
    int t = blockIdx.x * blockDim.x + threadIdx.x;
    int node = t / LPN;
    if (node >= Nn) return;
    int c = (t % LPN) * 8;
    int beg = __ldg(rowptr + node);
    int end = __ldg(rowptr + node + 1);

    float a0[8], a1[8];
#pragma unroll
    for (int q = 0; q < 8; q++) { a0[q] = 0.f; a1[q] = 0.f; }

    int e = beg;
    for (; e + 1 < end; e += 2) {
        int s0 = __ldg(col + e);
        int s1 = __ldg(col + e + 1);
        uint4 u0 = __ldg(reinterpret_cast<const uint4*>(X + (size_t)s0 * D + c));
        uint4 u1 = __ldg(reinterpret_cast<const uint4*>(X + (size_t)s1 * D + c));
        const __half2* h0 = reinterpret_cast<const __half2*>(&u0);
        const __half2* h1 = reinterpret_cast<const __half2*>(&u1);
#pragma unroll
        for (int q = 0; q < 4; q++) {
            float2 f0 = __half22float2(h0[q]);
            float2 f1 = __half22float2(h1[q]);
            a0[q * 2]     += f0.x;
            a0[q * 2 + 1] += f0.y;
            a1[q * 2]     += f1.x;
            a1[q * 2 + 1] += f1.y;
        }
    }
    if (e < end) {
        int s0 = __ldg(col + e);
        uint4 u0 = __ldg(reinterpret_cast<const uint4*>(X + (size_t)s0 * D + c));
        const __half2* h0 = reinterpret_cast<const __half2*>(&u0);
#pragma unroll
        for (int q = 0; q < 4; q++) {
            float2 f0 = __half22float2(h0[q]);
            a0[q * 2]     += f0.x;
            a0[q * 2 + 1] += f0.y;
        }
    }

    __half2 o0 = __floats2half2_rn(a0[0] + a1[0], a0[1] + a1[1]);
    __half2 o1 = __floats2half2_rn(a0[2] + a1[2], a0[3] + a1[3]);
    __half2 o2 = __floats2half2_rn(a0[4] + a1[4], a0[5] + a1[5]);
    __half2 o3 = __floats2half2_rn(a0[6] + a1[6], a0[7] + a1[7]);
    uint4 out;
    out.x = reinterpret_cast<uint32_t&>(o0);
    out.y = reinterpret_cast<uint32_t&>(o1);
    out.z = reinterpret_cast<uint32_t&>(o2);
    out.w = reinterpret_cast<uint32_t&>(o3);
    *reinterpret_cast<uint4*>(AGG + (size_t)node * D + c) = out;
}

// ------------------------------- pooling -----------------------------------

__device__ __forceinline__ int lower_bound_dev(const int* __restrict__ a, int n, int v) {
    int lo = 0, hi = n;
    while (lo < hi) {
        int m = (lo + hi) >> 1;
        if (a[m] < v) lo = m + 1; else hi = m;
    }
    return lo;
}

__global__ void pool_kernel(const __half* __restrict__ AGG, const float* __restrict__ innorm,
                            const float* __restrict__ b3, const int* __restrict__ gids,
                            float* __restrict__ out, int Nn) {
    int g = blockIdx.x;
    int lo = lower_bound_dev(gids, Nn, g);
    int hi = lower_bound_dev(gids, Nn, g + 1);
    int f = threadIdx.x & 63;
    int slot = threadIdx.x >> 6;
    float bf = b3[f];
    float sum = 0.f;
    for (int i = lo + slot; i < hi; i += 4)
        sum += fmaf(__half2float(AGG[(size_t)i * 64 + f]), innorm[i], bf);
    __shared__ float sh[256];
    sh[threadIdx.x] = sum;
    __syncthreads();
    if (slot == 0) {
        float tot = sh[f] + sh[64 + f] + sh[128 + f] + sh[192 + f];
        float cnt = (float)(hi - lo);
        out[g * 64 + f] = tot / fmaxf(cnt, 1.f);
    }
}

// ------------------------------- launch ------------------------------------

extern "C" void kernel_launch(void* const* d_in, const int* in_sizes, int n_in,
                              void* d_out, int out_size) {
    const float* emb = (const float*)d_in[0];
    const float* W1  = (const float*)d_in[1];
    const float* b1  = (const float*)d_in[2];
    const float* W2  = (const float*)d_in[3];
    const float* b2  = (const float*)d_in[4];
    const float* W3  = (const float*)d_in[5];
    const float* b3  = (const float*)d_in[6];
    const int*   src = (const int*)d_in[7];
    const int*   dst = (const int*)d_in[8];
    const int*   gid = (const int*)d_in[9];
    float* out = (float*)d_out;

    const int Nn = in_sizes[0] / 128;   // 100000
    const int E  = in_sizes[7];         // 1600000
    const int G  = out_size / 64;       // 64

    __half *X, *AGG;
    float *onrm, *inrm;
    int *indeg, *outdeg, *rowptr, *fillc, *colA, *bsums;
    __nv_bfloat16 *Wh, *Wl;
    cudaGetSymbolAddress((void**)&X,      g_X);
    cudaGetSymbolAddress((void**)&AGG,    g_AGG);
    cudaGetSymbolAddress((void**)&onrm,   g_outnorm);
    cudaGetSymbolAddress((void**)&inrm,   g_innorm);
    cudaGetSymbolAddress((void**)&indeg,  g_indeg);
    cudaGetSymbolAddress((void**)&outdeg, g_outdeg);
    cudaGetSymbolAddress((void**)&rowptr, g_rowptr);
    cudaGetSymbolAddress((void**)&fillc,  g_fill);
    cudaGetSymbolAddress((void**)&colA,   g_col);
    cudaGetSymbolAddress((void**)&bsums,  g_bsums);
    cudaGetSymbolAddress((void**)&Wh,     g_Wh);
    cudaGetSymbolAddress((void**)&Wl,     g_Wl);

    // dynamic smem: 2 * (A 64x80x2 + W N*80*2)
    const int smem128 = 2 * (10240 + 2 * 128 * 80);  // 61440
    const int smem64  = 2 * (10240 + 2 * 64 * 80);   // 40960
    cudaFuncSetAttribute(gemm_mma_kernel<128, 128, 0>,
                         cudaFuncAttributeMaxDynamicSharedMemorySize, smem128);
    cudaFuncSetAttribute(gemm_mma_kernel<128, 64, 1>,
                         cudaFuncAttributeMaxDynamicSharedMemorySize, smem64);
    cudaFuncSetAttribute(gemm_mma_kernel<64, 64, 1>,
                         cudaFuncAttributeMaxDynamicSharedMemorySize, smem64);

    const int T = 256;
    const int gemm_grid = (Nn + 63) / 64;
    const int nb_scan = (Nn + SCAN_BS - 1) / SCAN_BS;

    // 1: zero degrees + pre-split W (fused)
    prep_kernel<<<(Nn + T - 1) / T, T>>>(W1, W2, W3, Wh, Wl, indeg, outdeg, Nn);
    // 2: degree histograms
    hist_kernel<<<(E + T - 1) / T, T>>>(src, dst, outdeg, indeg, E);
    // 3: norms
    norm_kernel<<<(Nn + T - 1) / T, T>>>(outdeg, indeg, onrm, inrm, Nn);
    // 4: layer-1 GEMM  (ncu capture slot)
    gemm_mma_kernel<128, 128, 0><<<gemm_grid, T, smem128>>>(emb, Wh, Wl, nullptr,
                                                            onrm, inrm, X, Nn);
    // 5-7: CSR build
    scanA_kernel<<<nb_scan, SCAN_BS>>>(indeg, rowptr, bsums, Nn);
    scanBC_kernel<<<(Nn + 255) / 256, 256>>>(rowptr, fillc, bsums, nb_scan, Nn, E);
    fill_kernel<<<(E + T - 1) / T, T>>>(src, dst, fillc, colA, E);
    // 8: gather layer 1
    gather_kernel<128><<<(Nn * 16 + T - 1) / T, T>>>(X, rowptr, colA, AGG, Nn);

    // Layer 2
    gemm_mma_kernel<128, 64, 1><<<gemm_grid, T, smem64>>>(AGG, Wh + W2_OFF, Wl + W2_OFF,
                                                          b1, onrm, inrm, X, Nn);
    gather_kernel<64><<<(Nn * 8 + T - 1) / T, T>>>(X, rowptr, colA, AGG, Nn);

    // Layer 3
    gemm_mma_kernel<64, 64, 1><<<gemm_grid, T, smem64>>>(AGG, Wh + W3_OFF, Wl + W3_OFF,
                                                         b2, onrm, inrm, X, Nn);
    gather_kernel<64><<<(Nn * 8 + T - 1) / T, T>>>(X, rowptr, colA, AGG, Nn);

    // Pool
    pool_kernel<<<G, T>>>(AGG, inrm, b3, gid, out, Nn);
}

// round 13
// speedup vs baseline: 1.1923x; 1.0495x over previous
#include <cuda_runtime.h>
#include <cuda_bf16.h>
#include <cuda_fp16.h>
#include <cstdint>

// ---------------------------------------------------------------------------
// GCN: 3x (pointwise -> fp16x2 mma.sync GEMM -> CSR gather-sum) + mean pool
// R12->R13: GEMMs switch bf16x3 -> fp16x2. A is fp16 everywhere (emb converted
// once in prep; X/AGG already fp16), so the A-side split is EXACT and only
// W needs hi/lo fp16 terms: D = A@Wh + A@Wl. ldsm -25%, HMMA -33%, A traffic
// -50% in GEMM1. L1-wavefront pressure (79% in R12) is the targeted limiter.
// ---------------------------------------------------------------------------

#define MAX_NODES 100000
#define MAX_EDGES 1600000
#define MAX_FEATS 128
#define SCAN_BS 512

__device__ __half g_EMB16[MAX_NODES * MAX_FEATS]; // emb converted to fp16
__device__ __half g_X[MAX_NODES * MAX_FEATS];     // GEMM outputs, fp16
__device__ __half g_AGG[MAX_NODES * MAX_FEATS];   // gathered sums, fp16
__device__ float  g_outnorm[MAX_NODES];
__device__ float  g_innorm[MAX_NODES];
__device__ int    g_indeg[MAX_NODES];
__device__ int    g_outdeg[MAX_NODES];
__device__ int    g_rowptr[MAX_NODES + 1];
__device__ int    g_fill[MAX_NODES];
__device__ int    g_col[MAX_EDGES];
__device__ int    g_bsums[(MAX_NODES + SCAN_BS - 1) / SCAN_BS];
// Pre-split transposed weights (n-major, K contiguous), fp16 hi/lo: W1|W2|W3
__device__ __align__(16) __half g_Wh[28672];
__device__ __align__(16) __half g_Wl[28672];
#define W2_OFF 16384
#define W3_OFF 24576

// ----------------------------- helpers -------------------------------------

__device__ __forceinline__ uint32_t smem_u32(const void* p) {
    uint32_t a;
    asm("{ .reg .u64 t; cvta.to.shared.u64 t, %1; cvt.u32.u64 %0, t; }" : "=r"(a) : "l"(p));
    return a;
}

__device__ __forceinline__ void ldsm_x4(uint32_t* r, uint32_t addr) {
    asm volatile("ldmatrix.sync.aligned.m8n8.x4.shared.b16 {%0,%1,%2,%3}, [%4];"
                 : "=r"(r[0]), "=r"(r[1]), "=r"(r[2]), "=r"(r[3]) : "r"(addr));
}

__device__ __forceinline__ void mma_fp16(float* d, const uint32_t* a, const uint32_t* b) {
    asm volatile("mma.sync.aligned.m16n8k16.row.col.f32.f16.f16.f32 "
                 "{%0,%1,%2,%3}, {%4,%5,%6,%7}, {%8,%9}, {%0,%1,%2,%3};"
                 : "+f"(d[0]), "+f"(d[1]), "+f"(d[2]), "+f"(d[3])
                 : "r"(a[0]), "r"(a[1]), "r"(a[2]), "r"(a[3]), "r"(b[0]), "r"(b[1]));
}

// --------------- prep: convert emb->fp16, split W, zero degrees ------------

__global__ void prep_kernel(const float* __restrict__ emb, __half* __restrict__ emb16,
                            const float* __restrict__ W1, const float* __restrict__ W2,
                            const float* __restrict__ W3,
                            __half* __restrict__ Wh, __half* __restrict__ Wl,
                            int* __restrict__ indeg, int* __restrict__ outdeg,
                            int n, int ec4) {
    int i = blockIdx.x * blockDim.x + threadIdx.x;
    // emb -> fp16, one float4 per thread
    if (i < ec4) {
        float4 v = *reinterpret_cast<const float4*>(emb + (size_t)i * 4);
        __half2 h0 = __floats2half2_rn(v.x, v.y);
        __half2 h1 = __floats2half2_rn(v.z, v.w);
        uint2 o;
        o.x = reinterpret_cast<uint32_t&>(h0);
        o.y = reinterpret_cast<uint32_t&>(h1);
        *reinterpret_cast<uint2*>(emb16 + (size_t)i * 4) = o;
    }
    if (i < n) { indeg[i] = 0; outdeg[i] = 0; }
    if (i < 128 * 128) {
        int nn = i >> 7, k = i & 127;
        float w = W1[k * 128 + nn];
        __half h = __float2half_rn(w);
        Wh[i] = h;
        Wl[i] = __float2half_rn(w - __half2float(h));
    }
    if (i < 64 * 128) {
        int nn = i >> 7, k = i & 127;
        float w = W2[k * 64 + nn];
        __half h = __float2half_rn(w);
        Wh[W2_OFF + i] = h;
        Wl[W2_OFF + i] = __float2half_rn(w - __half2float(h));
    }
    if (i < 64 * 64) {
        int nn = i >> 6, k = i & 63;
        float w = W3[k * 64 + nn];
        __half h = __float2half_rn(w);
        Wh[W3_OFF + i] = h;
        Wl[W3_OFF + i] = __float2half_rn(w - __half2float(h));
    }
}

// --------------------------- CSR construction ------------------------------

__global__ void hist_kernel(const int* __restrict__ src, const int* __restrict__ dst,
                            int* __restrict__ outdeg, int* __restrict__ indeg, int E) {
    int i = blockIdx.x * blockDim.x + threadIdx.x;
    if (i < E) {
        atomicAdd(outdeg + src[i], 1);
        atomicAdd(indeg + dst[i], 1);
    }
}

__global__ void norm_kernel(const int* __restrict__ od, const int* __restrict__ id,
                            float* __restrict__ onrm, float* __restrict__ inrm, int n) {
    int i = blockIdx.x * blockDim.x + threadIdx.x;
    if (i < n) {
        onrm[i] = rsqrtf(fmaxf((float)od[i], 1.0f));
        inrm[i] = rsqrtf(fmaxf((float)id[i], 1.0f));
    }
}

__global__ void scanA_kernel(const int* __restrict__ deg, int* __restrict__ rowptr,
                             int* __restrict__ bsums, int n) {
    __shared__ int sh[SCAN_BS];
    int t = threadIdx.x;
    int i = blockIdx.x * SCAN_BS + t;
    int v = (i < n) ? deg[i] : 0;
    sh[t] = v;
    __syncthreads();
#pragma unroll
    for (int off = 1; off < SCAN_BS; off <<= 1) {
        int x = (t >= off) ? sh[t - off] : 0;
        __syncthreads();
        sh[t] += x;
        __syncthreads();
    }
    if (i < n) rowptr[i] = sh[t] - v;
    if (t == SCAN_BS - 1) bsums[blockIdx.x] = sh[t];
}

__global__ void scanBC_kernel(int* __restrict__ rowptr, int* __restrict__ fill,
                              const int* __restrict__ bsums, int nb, int n, int E) {
    __shared__ int pref[256];
    int t = threadIdx.x;
    int v = (t < nb) ? bsums[t] : 0;
    pref[t] = v;
    __syncthreads();
#pragma unroll
    for (int off = 1; off < 256; off <<= 1) {
        int x = (t >= off) ? pref[t - off] : 0;
        __syncthreads();
        pref[t] += x;
        __syncthreads();
    }
    int i = blockIdx.x * blockDim.x + t;
    if (i < n) {
        int b = i / SCAN_BS;
        int excl = pref[b] - bsums[b];
        int r = rowptr[i] + excl;
        rowptr[i] = r;
        fill[i] = r;
    }
    if (i == 0) rowptr[n] = E;
}

__global__ void fill_kernel(const int* __restrict__ src, const int* __restrict__ dst,
                            int* __restrict__ fill, int* __restrict__ col, int E) {
    int i = blockIdx.x * blockDim.x + threadIdx.x;
    if (i < E) {
        int p = atomicAdd(fill + dst[i], 1);
        col[p] = src[i];
    }
}

// --------------------------- fp16x2 GEMM -----------------------------------
// X[M,N] (fp16) = f(A[M,K]) @ W[K,N], CTA tile 64 x N, 256 threads (2x4 warps),
// 3 CTAs/SM. A fp16 in global (exact), W pre-split fp16 hi/lo (n-major).
// MODE 0: f(a)[r,k] = a[r,k] * outnorm[r]
// MODE 1: f(a)[r,k] = relu(a[r,k]*innorm[r] + bprev[k]) * outnorm[r]
// fp16x2: D = A@Wh + A@Wl, fp32 accum (mma.sync m16n8k16 f16).

template<int K, int N, int MODE>
__global__ __launch_bounds__(256, 3)
void gemm_mma_kernel(const __half* __restrict__ Ain,
                     const __half* __restrict__ Wh,
                     const __half* __restrict__ Wl,
                     const float* __restrict__ bprev,
                     const float* __restrict__ outnorm, const float* __restrict__ innorm,
                     __half* __restrict__ X, int M) {
    constexpr int BK = 32;
    constexpr int NCHUNK = K / BK;
    constexpr int WN = N / 4;        // warp tile cols (2x4 warp grid)
    constexpr int NT = WN / 8;       // 4 for N=128, 2 for N=64
    constexpr int MT = 2;
    constexpr int P = 40;            // smem pitch in halves (80B, LDSM-clean)
    constexpr int A_OFF = 0;
    constexpr int A_SZ = 64 * P * 2;             // 5120
    constexpr int W_OFF = A_SZ;
    constexpr int W_SZ = N * P * 2;              // hi region; lo at +W_SZ
    constexpr int BUFS = W_OFF + 2 * W_SZ;
    constexpr int WCNT = (N == 128) ? 2 : 1;     // W uint4 groups per thread

    extern __shared__ char smem[];
    const uint32_t sb = smem_u32(smem);
    const int tid = threadIdx.x;
    const int lane = tid & 31;
    const int wid = tid >> 5;        // 0..7
    const int warp_m = wid >> 2;     // 0..1
    const int warp_n = wid & 3;      // 0..3
    const int row0 = blockIdx.x * 64;

    // A-load mapping: 4 threads per row, each covers 8 cols (one uint4 of halves)
    const int arow = tid & 63;
    const int aq = tid >> 6;         // 0..3 -> cols [aq*8, aq*8+8)
    const int col0 = aq * 8;
    const int grow = row0 + arow;
    const bool valid = grow < M;
    const float on  = valid ? outnorm[grow] : 0.f;
    const float inn = (MODE == 1 && valid) ? innorm[grow] : 0.f;

    // ldmatrix per-lane bases
    const int a_r = warp_m * 32 + ((lane >> 3) & 1) * 8 + (lane & 7);
    const int a_k = (lane >> 4) * 8;
    const int b_n = warp_n * WN + (lane >> 4) * 8 + (lane & 7);
    const int b_k = ((lane >> 3) & 1) * 8;

    float acc[MT][NT][4];
#pragma unroll
    for (int i = 0; i < MT; i++)
#pragma unroll
        for (int j = 0; j < NT; j++)
#pragma unroll
            for (int q = 0; q < 4; q++) acc[i][j][q] = 0.f;

    float a8[8];
    uint4 whv[WCNT], wlv[WCNT];

    auto load_g = [&](int c) {
        const int kc = c * BK;
        uint4 u = make_uint4(0u, 0u, 0u, 0u);
        if (valid)
            u = *reinterpret_cast<const uint4*>(Ain + (size_t)grow * K + kc + col0);
        const __half2* hp = reinterpret_cast<const __half2*>(&u);
        float2 f0 = __half22float2(hp[0]);
        float2 f1 = __half22float2(hp[1]);
        float2 f2 = __half22float2(hp[2]);
        float2 f3 = __half22float2(hp[3]);
        if (MODE == 0) {
            a8[0] = f0.x * on; a8[1] = f0.y * on;
            a8[2] = f1.x * on; a8[3] = f1.y * on;
            a8[4] = f2.x * on; a8[5] = f2.y * on;
            a8[6] = f3.x * on; a8[7] = f3.y * on;
        } else {
            float4 b0 = *reinterpret_cast<const float4*>(bprev + kc + col0);
            float4 b1 = *reinterpret_cast<const float4*>(bprev + kc + col0 + 4);
            a8[0] = fmaxf(fmaf(f0.x, inn, b0.x), 0.f) * on;
            a8[1] = fmaxf(fmaf(f0.y, inn, b0.y), 0.f) * on;
            a8[2] = fmaxf(fmaf(f1.x, inn, b0.z), 0.f) * on;
            a8[3] = fmaxf(fmaf(f1.y, inn, b0.w), 0.f) * on;
            a8[4] = fmaxf(fmaf(f2.x, inn, b1.x), 0.f) * on;
            a8[5] = fmaxf(fmaf(f2.y, inn, b1.y), 0.f) * on;
            a8[6] = fmaxf(fmaf(f3.x, inn, b1.z), 0.f) * on;
            a8[7] = fmaxf(fmaf(f3.y, inn, b1.w), 0.f) * on;
        }
#pragma unroll
        for (int w = 0; w < WCNT; w++) {
            const int g = tid + w * 256;
            const int wn = g >> 2, wk8 = g & 3;
            const size_t woff = (size_t)wn * K + kc + wk8 * 8;
            whv[w] = *reinterpret_cast<const uint4*>(Wh + woff);
            wlv[w] = *reinterpret_cast<const uint4*>(Wl + woff);
        }
    };

    auto store_s = [&](int buf) {
        char* base = smem + buf * BUFS;
        __half2 h0 = __floats2half2_rn(a8[0], a8[1]);
        __half2 h1 = __floats2half2_rn(a8[2], a8[3]);
        __half2 h2 = __floats2half2_rn(a8[4], a8[5]);
        __half2 h3 = __floats2half2_rn(a8[6], a8[7]);
        uint4 av4;
        av4.x = reinterpret_cast<uint32_t&>(h0);
        av4.y = reinterpret_cast<uint32_t&>(h1);
        av4.z = reinterpret_cast<uint32_t&>(h2);
        av4.w = reinterpret_cast<uint32_t&>(h3);
        const uint32_t aoff = (uint32_t)arow * (P * 2) + col0 * 2;
        *reinterpret_cast<uint4*>(base + A_OFF + aoff) = av4;
#pragma unroll
        for (int w = 0; w < WCNT; w++) {
            const int g = tid + w * 256;
            const int wn = g >> 2, wk8 = g & 3;
            const uint32_t off = (uint32_t)wn * (P * 2) + wk8 * 16;
            *reinterpret_cast<uint4*>(base + W_OFF + off) = whv[w];
            *reinterpret_cast<uint4*>(base + W_OFF + W_SZ + off) = wlv[w];
        }
    };

    auto compute = [&](int buf) {
        const uint32_t ab = sb + buf * BUFS;
#pragma unroll
        for (int ks = 0; ks < 2; ks++) {
            uint32_t ah[MT][4];
#pragma unroll
            for (int i = 0; i < MT; i++) {
                const uint32_t addr = ab + A_OFF +
                    (uint32_t)(a_r + i * 16) * (P * 2) + (a_k + ks * 16) * 2;
                ldsm_x4(ah[i], addr);
            }
#pragma unroll
            for (int p = 0; p < NT / 2; p++) {
                uint32_t bh[4], bl[4];
                const uint32_t baddr = ab + W_OFF +
                    (uint32_t)(b_n + p * 16) * (P * 2) + (b_k + ks * 16) * 2;
                ldsm_x4(bh, baddr);
                ldsm_x4(bl, baddr + W_SZ);
#pragma unroll
                for (int i = 0; i < MT; i++)
#pragma unroll
                    for (int jj = 0; jj < 2; jj++) {
                        float* d = acc[i][p * 2 + jj];
                        mma_fp16(d, ah[i], bh + jj * 2);
                        mma_fp16(d, ah[i], bl + jj * 2);
                    }
            }
        }
    };

    load_g(0);
    store_s(0);
    __syncthreads();

    for (int c = 0; c < NCHUNK; c++) {
        if (c + 1 < NCHUNK) load_g(c + 1);
        compute(c & 1);
        if (c + 1 < NCHUNK) store_s((c + 1) & 1);
        __syncthreads();
    }

    // epilogue: fp32 acc -> fp16 X
#pragma unroll
    for (int i = 0; i < MT; i++) {
        const int r0 = row0 + warp_m * 32 + i * 16 + (lane >> 2);
#pragma unroll
        for (int j = 0; j < NT; j++) {
            const int n0 = warp_n * WN + j * 8 + (lane & 3) * 2;
            if (r0 < M)
                *reinterpret_cast<__half2*>(X + (size_t)r0 * N + n0) =
                    __floats2half2_rn(acc[i][j][0], acc[i][j][1]);
            if (r0 + 8 < M)
                *reinterpret_cast<__half2*>(X + (size_t)(r0 + 8) * N + n0) =
                    __floats2half2_rn(acc[i][j][2], acc[i][j][3]);
        }
    }
}

// ------------------------------ CSR gather ---------------------------------
// AGG[n] (fp16) = sum over e in [rowptr[n], rowptr[n+1]) of X[col[e]] (fp16)
// fp32 accumulation in registers; D/8 lanes per node; 2-edge unroll.

template<int D>
__global__ __launch_bounds__(256)
void gather_kernel(const __half* __restrict__ X, const int* __restrict__ rowptr,
                   const int* __restrict__ col, __half* __restrict__ AGG, int Nn) {
    constexpr int LPN = D / 8;   // 16 for D=128, 8 for D=64
    int t = blockIdx.x * blockDim.x + threadIdx.x;
    int node = t / LPN;
    if (node >= Nn) return;
    int c = (t % LPN) * 8;
    int beg = __ldg(rowptr + node);
    int end = __ldg(rowptr + node + 1);

    float a0[8], a1[8];
#pragma unroll
    for (int q = 0; q < 8; q++) { a0[q] = 0.f; a1[q] = 0.f; }

    int e = beg;
    for (; e + 1 < end; e += 2) {
        int s0 = __ldg(col + e);
        int s1 = __ldg(col + e + 1);
        uint4 u0 = __ldg(reinterpret_cast<const uint4*>(X + (size_t)s0 * D + c));
        uint4 u1 = __ldg(reinterpret_cast<const uint4*>(X + (size_t)s1 * D + c));
        const __half2* h0 = reinterpret_cast<const __half2*>(&u0);
        const __half2* h1 = reinterpret_cast<const __half2*>(&u1);
#pragma unroll
        for (int q = 0; q < 4; q++) {
            float2 f0 = __half22float2(h0[q]);
            float2 f1 = __half22float2(h1[q]);
            a0[q * 2]     += f0.x;
            a0[q * 2 + 1] += f0.y;
            a1[q * 2]     += f1.x;
            a1[q * 2 + 1] += f1.y;
        }
    }
    if (e < end) {
        int s0 = __ldg(col + e);
        uint4 u0 = __ldg(reinterpret_cast<const uint4*>(X + (size_t)s0 * D + c));
        const __half2* h0 = reinterpret_cast<const __half2*>(&u0);
#pragma unroll
        for (int q = 0; q < 4; q++) {
            float2 f0 = __half22float2(h0[q]);
            a0[q * 2]     += f0.x;
            a0[q * 2 + 1] += f0.y;
        }
    }

    __half2 o0 = __floats2half2_rn(a0[0] + a1[0], a0[1] + a1[1]);
    __half2 o1 = __floats2half2_rn(a0[2] + a1[2], a0[3] + a1[3]);
    __half2 o2 = __floats2half2_rn(a0[4] + a1[4], a0[5] + a1[5]);
    __half2 o3 = __floats2half2_rn(a0[6] + a1[6], a0[7] + a1[7]);
    uint4 out;
    out.x = reinterpret_cast<uint32_t&>(o0);
    out.y = reinterpret_cast<uint32_t&>(o1);
    out.z = reinterpret_cast<uint32_t&>(o2);
    out.w = reinterpret_cast<uint32_t&>(o3);
    *reinterpret_cast<uint4*>(AGG + (size_t)node * D + c) = out;
}

// ------------------------------- pooling -----------------------------------

__device__ __forceinline__ int lower_bound_dev(const int* __restrict__ a, int n, int v) {
    int lo = 0, hi = n;
    while (lo < hi) {
        int m = (lo + hi) >> 1;
        if (a[m] < v) lo = m + 1; else hi = m;
    }
    return lo;
}

__global__ void pool_kernel(const __half* __restrict__ AGG, const float* __restrict__ innorm,
                            const float* __restrict__ b3, const int* __restrict__ gids,
                            float* __restrict__ out, int Nn) {
    int g = blockIdx.x;
    int lo = lower_bound_dev(gids, Nn, g);
    int hi = lower_bound_dev(gids, Nn, g + 1);
    int f = threadIdx.x & 63;
    int slot = threadIdx.x >> 6;
    float bf = b3[f];
    float sum = 0.f;
    for (int i = lo + slot; i < hi; i += 4)
        sum += fmaf(__half2float(AGG[(size_t)i * 64 + f]), innorm[i], bf);
    __shared__ float sh[256];
    sh[threadIdx.x] = sum;
    __syncthreads();
    if (slot == 0) {
        float tot = sh[f] + sh[64 + f] + sh[128 + f] + sh[192 + f];
        float cnt = (float)(hi - lo);
        out[g * 64 + f] = tot / fmaxf(cnt, 1.f);
    }
}

// ------------------------------- launch ------------------------------------

extern "C" void kernel_launch(void* const* d_in, const int* in_sizes, int n_in,
                              void* d_out, int out_size) {
    const float* emb = (const float*)d_in[0];
    const float* W1  = (const float*)d_in[1];
    const float* b1  = (const float*)d_in[2];
    const float* W2  = (const float*)d_in[3];
    const float* b2  = (const float*)d_in[4];
    const float* W3  = (const float*)d_in[5];
    const float* b3  = (const float*)d_in[6];
    const int*   src = (const int*)d_in[7];
    const int*   dst = (const int*)d_in[8];
    const int*   gid = (const int*)d_in[9];
    float* out = (float*)d_out;

    const int Nn = in_sizes[0] / 128;   // 100000
    const int E  = in_sizes[7];         // 1600000
    const int G  = out_size / 64;       // 64

    __half *EMB16, *X, *AGG, *Wh, *Wl;
    float *onrm, *inrm;
    int *indeg, *outdeg, *rowptr, *fillc, *colA, *bsums;
    cudaGetSymbolAddress((void**)&EMB16,  g_EMB16);
    cudaGetSymbolAddress((void**)&X,      g_X);
    cudaGetSymbolAddress((void**)&AGG,    g_AGG);
    cudaGetSymbolAddress((void**)&onrm,   g_outnorm);
    cudaGetSymbolAddress((void**)&inrm,   g_innorm);
    cudaGetSymbolAddress((void**)&indeg,  g_indeg);
    cudaGetSymbolAddress((void**)&outdeg, g_outdeg);
    cudaGetSymbolAddress((void**)&rowptr, g_rowptr);
    cudaGetSymbolAddress((void**)&fillc,  g_fill);
    cudaGetSymbolAddress((void**)&colA,   g_col);
    cudaGetSymbolAddress((void**)&bsums,  g_bsums);
    cudaGetSymbolAddress((void**)&Wh,     g_Wh);
    cudaGetSymbolAddress((void**)&Wl,     g_Wl);

    // dynamic smem: 2 * (A 64x80 + W hi/lo N*80*2)
    const int smem128 = 2 * (5120 + 2 * 128 * 80);   // 51200
    const int smem64  = 2 * (5120 + 2 * 64 * 80);    // 30720
    cudaFuncSetAttribute(gemm_mma_kernel<128, 128, 0>,
                         cudaFuncAttributeMaxDynamicSharedMemorySize, smem128);
    cudaFuncSetAttribute(gemm_mma_kernel<128, 64, 1>,
                         cudaFuncAttributeMaxDynamicSharedMemorySize, smem64);
    cudaFuncSetAttribute(gemm_mma_kernel<64, 64, 1>,
                         cudaFuncAttributeMaxDynamicSharedMemorySize, smem64);

    const int T = 256;
    const int gemm_grid = (Nn + 63) / 64;
    const int nb_scan = (Nn + SCAN_BS - 1) / SCAN_BS;
    const int ec4 = Nn * 32;            // float4 count of emb

    // 1: emb->fp16 + W split + zero degrees (fused)
    prep_kernel<<<(ec4 + T - 1) / T, T>>>(emb, EMB16, W1, W2, W3, Wh, Wl,
                                          indeg, outdeg, Nn, ec4);
    // 2: degree histograms
    hist_kernel<<<(E + T - 1) / T, T>>>(src, dst, outdeg, indeg, E);
    // 3: norms
    norm_kernel<<<(Nn + T - 1) / T, T>>>(outdeg, indeg, onrm, inrm, Nn);
    // 4: layer-1 GEMM  (ncu capture slot)
    gemm_mma_kernel<128, 128, 0><<<gemm_grid, T, smem128>>>(EMB16, Wh, Wl, nullptr,
                                                            onrm, inrm, X, Nn);
    // 5-7: CSR build
    scanA_kernel<<<nb_scan, SCAN_BS>>>(indeg, rowptr, bsums, Nn);
    scanBC_kernel<<<(Nn + 255) / 256, 256>>>(rowptr, fillc, bsums, nb_scan, Nn, E);
    fill_kernel<<<(E + T - 1) / T, T>>>(src, dst, fillc, colA, E);
    // 8: gather layer 1
    gather_kernel<128><<<(Nn * 16 + T - 1) / T, T>>>(X, rowptr, colA, AGG, Nn);

    // Layer 2
    gemm_mma_kernel<128, 64, 1><<<gemm_grid, T, smem64>>>(AGG, Wh + W2_OFF, Wl + W2_OFF,
                                                          b1, onrm, inrm, X, Nn);
    gather_kernel<64><<<(Nn * 8 + T - 1) / T, T>>>(X, rowptr, colA, AGG, Nn);

    // Layer 3
    gemm_mma_kernel<64, 64, 1><<<gemm_grid, T, smem64>>>(AGG, Wh + W3_OFF, Wl + W3_OFF,
                                                         b2, onrm, inrm, X, Nn);
    gather_kernel<64><<<(Nn * 8 + T - 1) / T, T>>>(X, rowptr, colA, AGG, Nn);

    // Pool
    pool_kernel<<<G, T>>>(AGG, inrm, b3, gid, out, Nn);
}

// round 14
// speedup vs baseline: 1.2617x; 1.0582x over previous
#include <cuda_runtime.h>
#include <cuda_bf16.h>
#include <cuda_fp16.h>
#include <cstdint>

// ---------------------------------------------------------------------------
// GCN: 3x (pointwise -> fp16x2 mma.sync GEMM -> CSR gather-sum) + mean pool
// R13->R14: GEMMs go persistent-ish. Each CTA loads the FULL pre-split W
// (fp16 hi/lo) into smem ONCE, then grid-strides over 64-row tiles with only
// the A chunk double-buffered. Removes per-chunk W LDG/STS (~36% of L1
// wavefronts, R13 L1=77.6%) and cuts redundant W L2 traffic 100MB -> 20MB.
// ---------------------------------------------------------------------------

#define MAX_NODES 100000
#define MAX_EDGES 1600000
#define MAX_FEATS 128
#define SCAN_BS 512
#define NSM 148

__device__ __half g_EMB16[MAX_NODES * MAX_FEATS]; // emb converted to fp16
__device__ __half g_X[MAX_NODES * MAX_FEATS];     // GEMM outputs, fp16
__device__ __half g_AGG[MAX_NODES * MAX_FEATS];   // gathered sums, fp16
__device__ float  g_outnorm[MAX_NODES];
__device__ float  g_innorm[MAX_NODES];
__device__ int    g_indeg[MAX_NODES];
__device__ int    g_outdeg[MAX_NODES];
__device__ int    g_rowptr[MAX_NODES + 1];
__device__ int    g_fill[MAX_NODES];
__device__ int    g_col[MAX_EDGES];
__device__ int    g_bsums[(MAX_NODES + SCAN_BS - 1) / SCAN_BS];
// Pre-split transposed weights (n-major, K contiguous), fp16 hi/lo: W1|W2|W3
__device__ __align__(16) __half g_Wh[28672];
__device__ __align__(16) __half g_Wl[28672];
#define W2_OFF 16384
#define W3_OFF 24576

// ----------------------------- helpers -------------------------------------

__device__ __forceinline__ uint32_t smem_u32(const void* p) {
    uint32_t a;
    asm("{ .reg .u64 t; cvta.to.shared.u64 t, %1; cvt.u32.u64 %0, t; }" : "=r"(a) : "l"(p));
    return a;
}

__device__ __forceinline__ void ldsm_x4(uint32_t* r, uint32_t addr) {
    asm volatile("ldmatrix.sync.aligned.m8n8.x4.shared.b16 {%0,%1,%2,%3}, [%4];"
                 : "=r"(r[0]), "=r"(r[1]), "=r"(r[2]), "=r"(r[3]) : "r"(addr));
}

__device__ __forceinline__ void mma_fp16(float* d, const uint32_t* a, const uint32_t* b) {
    asm volatile("mma.sync.aligned.m16n8k16.row.col.f32.f16.f16.f32 "
                 "{%0,%1,%2,%3}, {%4,%5,%6,%7}, {%8,%9}, {%0,%1,%2,%3};"
                 : "+f"(d[0]), "+f"(d[1]), "+f"(d[2]), "+f"(d[3])
                 : "r"(a[0]), "r"(a[1]), "r"(a[2]), "r"(a[3]), "r"(b[0]), "r"(b[1]));
}

// --------------- prep: convert emb->fp16, split W, zero degrees ------------

__global__ void prep_kernel(const float* __restrict__ emb, __half* __restrict__ emb16,
                            const float* __restrict__ W1, const float* __restrict__ W2,
                            const float* __restrict__ W3,
                            __half* __restrict__ Wh, __half* __restrict__ Wl,
                            int* __restrict__ indeg, int* __restrict__ outdeg,
                            int n, int ec4) {
    int i = blockIdx.x * blockDim.x + threadIdx.x;
    if (i < ec4) {
        float4 v = *reinterpret_cast<const float4*>(emb + (size_t)i * 4);
        __half2 h0 = __floats2half2_rn(v.x, v.y);
        __half2 h1 = __floats2half2_rn(v.z, v.w);
        uint2 o;
        o.x = reinterpret_cast<uint32_t&>(h0);
        o.y = reinterpret_cast<uint32_t&>(h1);
        *reinterpret_cast<uint2*>(emb16 + (size_t)i * 4) = o;
    }
    if (i < n) { indeg[i] = 0; outdeg[i] = 0; }
    if (i < 128 * 128) {
        int nn = i >> 7, k = i & 127;
        float w = W1[k * 128 + nn];
        __half h = __float2half_rn(w);
        Wh[i] = h;
        Wl[i] = __float2half_rn(w - __half2float(h));
    }
    if (i < 64 * 128) {
        int nn = i >> 7, k = i & 127;
        float w = W2[k * 64 + nn];
        __half h = __float2half_rn(w);
        Wh[W2_OFF + i] = h;
        Wl[W2_OFF + i] = __float2half_rn(w - __half2float(h));
    }
    if (i < 64 * 64) {
        int nn = i >> 6, k = i & 63;
        float w = W3[k * 64 + nn];
        __half h = __float2half_rn(w);
        Wh[W3_OFF + i] = h;
        Wl[W3_OFF + i] = __float2half_rn(w - __half2float(h));
    }
}

// --------------------------- CSR construction ------------------------------

__global__ void hist_kernel(const int* __restrict__ src, const int* __restrict__ dst,
                            int* __restrict__ outdeg, int* __restrict__ indeg, int E) {
    int i = blockIdx.x * blockDim.x + threadIdx.x;
    if (i < E) {
        atomicAdd(outdeg + src[i], 1);
        atomicAdd(indeg + dst[i], 1);
    }
}

__global__ void norm_kernel(const int* __restrict__ od, const int* __restrict__ id,
                            float* __restrict__ onrm, float* __restrict__ inrm, int n) {
    int i = blockIdx.x * blockDim.x + threadIdx.x;
    if (i < n) {
        onrm[i] = rsqrtf(fmaxf((float)od[i], 1.0f));
        inrm[i] = rsqrtf(fmaxf((float)id[i], 1.0f));
    }
}

__global__ void scanA_kernel(const int* __restrict__ deg, int* __restrict__ rowptr,
                             int* __restrict__ bsums, int n) {
    __shared__ int sh[SCAN_BS];
    int t = threadIdx.x;
    int i = blockIdx.x * SCAN_BS + t;
    int v = (i < n) ? deg[i] : 0;
    sh[t] = v;
    __syncthreads();
#pragma unroll
    for (int off = 1; off < SCAN_BS; off <<= 1) {
        int x = (t >= off) ? sh[t - off] : 0;
        __syncthreads();
        sh[t] += x;
        __syncthreads();
    }
    if (i < n) rowptr[i] = sh[t] - v;
    if (t == SCAN_BS - 1) bsums[blockIdx.x] = sh[t];
}

__global__ void scanBC_kernel(int* __restrict__ rowptr, int* __restrict__ fill,
                              const int* __restrict__ bsums, int nb, int n, int E) {
    __shared__ int pref[256];
    int t = threadIdx.x;
    int v = (t < nb) ? bsums[t] : 0;
    pref[t] = v;
    __syncthreads();
#pragma unroll
    for (int off = 1; off < 256; off <<= 1) {
        int x = (t >= off) ? pref[t - off] : 0;
        __syncthreads();
        pref[t] += x;
        __syncthreads();
    }
    int i = blockIdx.x * blockDim.x + t;
    if (i < n) {
        int b = i / SCAN_BS;
        int excl = pref[b] - bsums[b];
        int r = rowptr[i] + excl;
        rowptr[i] = r;
        fill[i] = r;
    }
    if (i == 0) rowptr[n] = E;
}

__global__ void fill_kernel(const int* __restrict__ src, const int* __restrict__ dst,
                            int* __restrict__ fill, int* __restrict__ col, int E) {
    int i = blockIdx.x * blockDim.x + threadIdx.x;
    if (i < E) {
        int p = atomicAdd(fill + dst[i], 1);
        col[p] = src[i];
    }
}

// --------------------------- fp16x2 GEMM (persistent) ----------------------
// X[M,N] (fp16) = f(A[M,K]) @ W[K,N]; 256 threads (2x4 warps), OCC CTAs/SM.
// Full W (fp16 hi/lo) loaded to smem ONCE per CTA; CTA grid-strides over
// 64-row tiles; only A chunk (BK=32) is double-buffered.
// MODE 0: f(a)[r,k] = a[r,k] * outnorm[r]
// MODE 1: f(a)[r,k] = relu(a[r,k]*innorm[r] + bprev[k]) * outnorm[r]
// fp16x2: D = A@Wh + A@Wl, fp32 accum (mma.sync m16n8k16 f16).

template<int K, int N, int MODE, int OCC>
__global__ __launch_bounds__(256, OCC)
void gemm_mma_kernel(const __half* __restrict__ Ain,
                     const __half* __restrict__ Wh,
                     const __half* __restrict__ Wl,
                     const float* __restrict__ bprev,
                     const float* __restrict__ outnorm, const float* __restrict__ innorm,
                     __half* __restrict__ X, int M, int ntiles) {
    constexpr int BK = 32;
    constexpr int NCHUNK = K / BK;
    constexpr int WN = N / 4;            // warp tile cols (2x4 warp grid)
    constexpr int NT = WN / 8;           // 4 for N=128, 2 for N=64
    constexpr int MT = 2;
    constexpr int P = 40;                // A smem pitch (halves), 80B
    constexpr int KP = K + 8;            // W smem pitch (halves); 8-row ldsm clean
    constexpr int A_SZ = 64 * P * 2;     // 5120 per buffer
    constexpr int W_OFF = 2 * A_SZ;      // W region after A double buffer
    constexpr int W_SZ = N * KP * 2;     // hi; lo at +W_SZ
    constexpr int K8 = K / 8;            // uint4 per W row

    extern __shared__ char smem[];
    const uint32_t sb = smem_u32(smem);
    const int tid = threadIdx.x;
    const int lane = tid & 31;
    const int wid = tid >> 5;            // 0..7
    const int warp_m = wid >> 2;         // 0..1
    const int warp_n = wid & 3;          // 0..3

    // ---- load full W into smem once ----
    for (int idx = tid; idx < N * K8; idx += 256) {
        const int wn = idx / K8;
        const int wk8 = idx % K8;
        const size_t goff = (size_t)wn * K + wk8 * 8;
        uint4 h = *reinterpret_cast<const uint4*>(Wh + goff);
        uint4 l = *reinterpret_cast<const uint4*>(Wl + goff);
        const uint32_t off = (uint32_t)wn * (KP * 2) + wk8 * 16;
        *reinterpret_cast<uint4*>(smem + W_OFF + off) = h;
        *reinterpret_cast<uint4*>(smem + W_OFF + W_SZ + off) = l;
    }

    // A-load mapping: 4 threads per row, each covers 8 cols (one uint4)
    const int arow = tid & 63;
    const int aq = tid >> 6;             // 0..3
    const int col0 = aq * 8;

    // ldmatrix per-lane bases
    const int a_r = warp_m * 32 + ((lane >> 3) & 1) * 8 + (lane & 7);
    const int a_k = (lane >> 4) * 8;
    const int b_n = warp_n * WN + (lane >> 4) * 8 + (lane & 7);
    const int b_k = ((lane >> 3) & 1) * 8;

    // per-tile state (captured by reference in lambdas)
    int grow = 0;
    bool valid = false;
    float on = 0.f, inn = 0.f;
    float a8[8];
    float acc[MT][NT][4];

    auto load_g = [&](int c) {
        const int kc = c * BK;
        uint4 u = make_uint4(0u, 0u, 0u, 0u);
        if (valid)
            u = *reinterpret_cast<const uint4*>(Ain + (size_t)grow * K + kc + col0);
        const __half2* hp = reinterpret_cast<const __half2*>(&u);
        float2 f0 = __half22float2(hp[0]);
        float2 f1 = __half22float2(hp[1]);
        float2 f2 = __half22float2(hp[2]);
        float2 f3 = __half22float2(hp[3]);
        if (MODE == 0) {
            a8[0] = f0.x * on; a8[1] = f0.y * on;
            a8[2] = f1.x * on; a8[3] = f1.y * on;
            a8[4] = f2.x * on; a8[5] = f2.y * on;
            a8[6] = f3.x * on; a8[7] = f3.y * on;
        } else {
            float4 b0 = *reinterpret_cast<const float4*>(bprev + kc + col0);
            float4 b1 = *reinterpret_cast<const float4*>(bprev + kc + col0 + 4);
            a8[0] = fmaxf(fmaf(f0.x, inn, b0.x), 0.f) * on;
            a8[1] = fmaxf(fmaf(f0.y, inn, b0.y), 0.f) * on;
            a8[2] = fmaxf(fmaf(f1.x, inn, b0.z), 0.f) * on;
            a8[3] = fmaxf(fmaf(f1.y, inn, b0.w), 0.f) * on;
            a8[4] = fmaxf(fmaf(f2.x, inn, b1.x), 0.f) * on;
            a8[5] = fmaxf(fmaf(f2.y, inn, b1.y), 0.f) * on;
            a8[6] = fmaxf(fmaf(f3.x, inn, b1.z), 0.f) * on;
            a8[7] = fmaxf(fmaf(f3.y, inn, b1.w), 0.f) * on;
        }
    };

    auto store_s = [&](int buf) {
        char* base = smem + buf * A_SZ;
        __half2 h0 = __floats2half2_rn(a8[0], a8[1]);
        __half2 h1 = __floats2half2_rn(a8[2], a8[3]);
        __half2 h2 = __floats2half2_rn(a8[4], a8[5]);
        __half2 h3 = __floats2half2_rn(a8[6], a8[7]);
        uint4 av4;
        av4.x = reinterpret_cast<uint32_t&>(h0);
        av4.y = reinterpret_cast<uint32_t&>(h1);
        av4.z = reinterpret_cast<uint32_t&>(h2);
        av4.w = reinterpret_cast<uint32_t&>(h3);
        const uint32_t aoff = (uint32_t)arow * (P * 2) + col0 * 2;
        *reinterpret_cast<uint4*>(base + aoff) = av4;
    };

    auto compute = [&](int buf, int c) {
        const uint32_t aB = sb + buf * A_SZ;
        const uint32_t wB = sb + W_OFF;
        const int kchunk = c * BK;
#pragma unroll
        for (int ks = 0; ks < 2; ks++) {
            uint32_t ah[MT][4];
#pragma unroll
            for (int i = 0; i < MT; i++) {
                const uint32_t addr = aB +
                    (uint32_t)(a_r + i * 16) * (P * 2) + (a_k + ks * 16) * 2;
                ldsm_x4(ah[i], addr);
            }
#pragma unroll
            for (int p = 0; p < NT / 2; p++) {
                uint32_t bh[4], bl[4];
                const uint32_t baddr = wB +
                    (uint32_t)(b_n + p * 16) * (KP * 2) +
                    (kchunk + b_k + ks * 16) * 2;
                ldsm_x4(bh, baddr);
                ldsm_x4(bl, baddr + W_SZ);
#pragma unroll
                for (int i = 0; i < MT; i++)
#pragma unroll
                    for (int jj = 0; jj < 2; jj++) {
                        float* d = acc[i][p * 2 + jj];
                        mma_fp16(d, ah[i], bh + jj * 2);
                        mma_fp16(d, ah[i], bl + jj * 2);
                    }
            }
        }
    };

    // ---- grid-stride over 64-row tiles ----
    for (int tile = blockIdx.x; tile < ntiles; tile += gridDim.x) {
        const int row0 = tile * 64;
        grow = row0 + arow;
        valid = grow < M;
        on  = valid ? outnorm[grow] : 0.f;
        inn = (MODE == 1 && valid) ? innorm[grow] : 0.f;

#pragma unroll
        for (int i = 0; i < MT; i++)
#pragma unroll
            for (int j = 0; j < NT; j++)
#pragma unroll
                for (int q = 0; q < 4; q++) acc[i][j][q] = 0.f;

        load_g(0);
        store_s(0);
        __syncthreads();

        for (int c = 0; c < NCHUNK; c++) {
            if (c + 1 < NCHUNK) load_g(c + 1);
            compute(c & 1, c);
            if (c + 1 < NCHUNK) store_s((c + 1) & 1);
            __syncthreads();
        }

        // epilogue: fp32 acc -> fp16 X
#pragma unroll
        for (int i = 0; i < MT; i++) {
            const int r0 = row0 + warp_m * 32 + i * 16 + (lane >> 2);
#pragma unroll
            for (int j = 0; j < NT; j++) {
                const int n0 = warp_n * WN + j * 8 + (lane & 3) * 2;
                if (r0 < M)
                    *reinterpret_cast<__half2*>(X + (size_t)r0 * N + n0) =
                        __floats2half2_rn(acc[i][j][0], acc[i][j][1]);
                if (r0 + 8 < M)
                    *reinterpret_cast<__half2*>(X + (size_t)(r0 + 8) * N + n0) =
                        __floats2half2_rn(acc[i][j][2], acc[i][j][3]);
            }
        }
    }
}

// ------------------------------ CSR gather ---------------------------------
// AGG[n] (fp16) = sum over e in [rowptr[n], rowptr[n+1]) of X[col[e]] (fp16)
// fp32 accumulation in registers; D/8 lanes per node; 2-edge unroll.

template<int D>
__global__ __launch_bounds__(256)
void gather_kernel(const __half* __restrict__ X, const int* __restrict__ rowptr,
                   const int* __restrict__ col, __half* __restrict__ AGG, int Nn) {
    constexpr int LPN = D / 8;   // 16 for D=128, 8 for D=64
    int t = blockIdx.x * blockDim.x + threadIdx.x;
    int node = t / LPN;
    if (node >= Nn) return;
    int c = (t % LPN) * 8;
    int beg = __ldg(rowptr + node);
    int end = __ldg(rowptr + node + 1);

    float a0[8], a1[8];
#pragma unroll
    for (int q = 0; q < 8; q++) { a0[q] = 0.f; a1[q] = 0.f; }

    int e = beg;
    for (; e + 1 < end; e += 2) {
        int s0 = __ldg(col + e);
        int s1 = __ldg(col + e + 1);
        uint4 u0 = __ldg(reinterpret_cast<const uint4*>(X + (size_t)s0 * D + c));
        uint4 u1 = __ldg(reinterpret_cast<const uint4*>(X + (size_t)s1 * D + c));
        const __half2* h0 = reinterpret_cast<const __half2*>(&u0);
        const __half2* h1 = reinterpret_cast<const __half2*>(&u1);
#pragma unroll
        for (int q = 0; q < 4; q++) {
            float2 f0 = __half22float2(h0[q]);
            float2 f1 = __half22float2(h1[q]);
            a0[q * 2]     += f0.x;
            a0[q * 2 + 1] += f0.y;
            a1[q * 2]     += f1.x;
            a1[q * 2 + 1] += f1.y;
        }
    }
    if (e < end) {
        int s0 = __ldg(col + e);
        uint4 u0 = __ldg(reinterpret_cast<const uint4*>(X + (size_t)s0 * D + c));
        const __half2* h0 = reinterpret_cast<const __half2*>(&u0);
#pragma unroll
        for (int q = 0; q < 4; q++) {
            float2 f0 = __half22float2(h0[q]);
            a0[q * 2]     += f0.x;
            a0[q * 2 + 1] += f0.y;
        }
    }

    __half2 o0 = __floats2half2_rn(a0[0] + a1[0], a0[1] + a1[1]);
    __half2 o1 = __floats2half2_rn(a0[2] + a1[2], a0[3] + a1[3]);
    __half2 o2 = __floats2half2_rn(a0[4] + a1[4], a0[5] + a1[5]);
    __half2 o3 = __floats2half2_rn(a0[6] + a1[6], a0[7] + a1[7]);
    uint4 out;
    out.x = reinterpret_cast<uint32_t&>(o0);
    out.y = reinterpret_cast<uint32_t&>(o1);
    out.z = reinterpret_cast<uint32_t&>(o2);
    out.w = reinterpret_cast<uint32_t&>(o3);
    *reinterpret_cast<uint4*>(AGG + (size_t)node * D + c) = out;
}

// ------------------------------- pooling -----------------------------------

__device__ __forceinline__ int lower_bound_dev(const int* __restrict__ a, int n, int v) {
    int lo = 0, hi = n;
    while (lo < hi) {
        int m = (lo + hi) >> 1;
        if (a[m] < v) lo = m + 1; else hi = m;
    }
    return lo;
}

__global__ void pool_kernel(const __half* __restrict__ AGG, const float* __restrict__ innorm,
                            const float* __restrict__ b3, const int* __restrict__ gids,
                            float* __restrict__ out, int Nn) {
    int g = blockIdx.x;
    int lo = lower_bound_dev(gids, Nn, g);
    int hi = lower_bound_dev(gids, Nn, g + 1);
    int f = threadIdx.x & 63;
    int slot = threadIdx.x >> 6;
    float bf = b3[f];
    float sum = 0.f;
    for (int i = lo + slot; i < hi; i += 4)
        sum += fmaf(__half2float(AGG[(size_t)i * 64 + f]), innorm[i], bf);
    __shared__ float sh[256];
    sh[threadIdx.x] = sum;
    __syncthreads();
    if (slot == 0) {
        float tot = sh[f] + sh[64 + f] + sh[128 + f] + sh[192 + f];
        float cnt = (float)(hi - lo);
        out[g * 64 + f] = tot / fmaxf(cnt, 1.f);
    }
}

// ------------------------------- launch ------------------------------------

extern "C" void kernel_launch(void* const* d_in, const int* in_sizes, int n_in,
                              void* d_out, int out_size) {
    const float* emb = (const float*)d_in[0];
    const float* W1  = (const float*)d_in[1];
    const float* b1  = (const float*)d_in[2];
    const float* W2  = (const float*)d_in[3];
    const float* b2  = (const float*)d_in[4];
    const float* W3  = (const float*)d_in[5];
    const float* b3  = (const float*)d_in[6];
    const int*   src = (const int*)d_in[7];
    const int*   dst = (const int*)d_in[8];
    const int*   gid = (const int*)d_in[9];
    float* out = (float*)d_out;

    const int Nn = in_sizes[0] / 128;   // 100000
    const int E  = in_sizes[7];         // 1600000
    const int G  = out_size / 64;       // 64

    __half *EMB16, *X, *AGG, *Wh, *Wl;
    float *onrm, *inrm;
    int *indeg, *outdeg, *rowptr, *fillc, *colA, *bsums;
    cudaGetSymbolAddress((void**)&EMB16,  g_EMB16);
    cudaGetSymbolAddress((void**)&X,      g_X);
    cudaGetSymbolAddress((void**)&AGG,    g_AGG);
    cudaGetSymbolAddress((void**)&onrm,   g_outnorm);
    cudaGetSymbolAddress((void**)&inrm,   g_innorm);
    cudaGetSymbolAddress((void**)&indeg,  g_indeg);
    cudaGetSymbolAddress((void**)&outdeg, g_outdeg);
    cudaGetSymbolAddress((void**)&rowptr, g_rowptr);
    cudaGetSymbolAddress((void**)&fillc,  g_fill);
    cudaGetSymbolAddress((void**)&colA,   g_col);
    cudaGetSymbolAddress((void**)&bsums,  g_bsums);
    cudaGetSymbolAddress((void**)&Wh,     g_Wh);
    cudaGetSymbolAddress((void**)&Wl,     g_Wl);

    // dynamic smem: 2*A_SZ + 2*W_SZ
    // GEMM1 (K=128,N=128): 10240 + 2*128*136*2 = 79872  -> OCC 2
    // GEMM2 (K=128,N=64):  10240 + 2*64*136*2  = 45056  -> OCC 3
    // GEMM3 (K=64, N=64):  10240 + 2*64*72*2   = 28672  -> OCC 3
    const int smem1 = 2 * 5120 + 2 * 128 * 136 * 2;
    const int smem2 = 2 * 5120 + 2 * 64 * 136 * 2;
    const int smem3 = 2 * 5120 + 2 * 64 * 72 * 2;
    cudaFuncSetAttribute(gemm_mma_kernel<128, 128, 0, 2>,
                         cudaFuncAttributeMaxDynamicSharedMemorySize, smem1);
    cudaFuncSetAttribute(gemm_mma_kernel<128, 64, 1, 3>,
                         cudaFuncAttributeMaxDynamicSharedMemorySize, smem2);
    cudaFuncSetAttribute(gemm_mma_kernel<64, 64, 1, 3>,
                         cudaFuncAttributeMaxDynamicSharedMemorySize, smem3);

    const int T = 256;
    const int ntiles = (Nn + 63) / 64;           // 1563
    const int grid1 = (ntiles < NSM * 2) ? ntiles : NSM * 2;   // 296
    const int grid23 = (ntiles < NSM * 3) ? ntiles : NSM * 3;  // 444
    const int nb_scan = (Nn + SCAN_BS - 1) / SCAN_BS;
    const int ec4 = Nn * 32;            // float4 count of emb

    // 1: emb->fp16 + W split + zero degrees (fused)
    prep_kernel<<<(ec4 + T - 1) / T, T>>>(emb, EMB16, W1, W2, W3, Wh, Wl,
                                          indeg, outdeg, Nn, ec4);
    // 2: degree histograms
    hist_kernel<<<(E + T - 1) / T, T>>>(src, dst, outdeg, indeg, E);
    // 3: norms
    norm_kernel<<<(Nn + T - 1) / T, T>>>(outdeg, indeg, onrm, inrm, Nn);
    // 4: layer-1 GEMM  (ncu capture slot)
    gemm_mma_kernel<128, 128, 0, 2><<<grid1, T, smem1>>>(EMB16, Wh, Wl, nullptr,
                                                         onrm, inrm, X, Nn, ntiles);
    // 5-7: CSR build
    scanA_kernel<<<nb_scan, SCAN_BS>>>(indeg, rowptr, bsums, Nn);
    scanBC_kernel<<<(Nn + 255) / 256, 256>>>(rowptr, fillc, bsums, nb_scan, Nn, E);
    fill_kernel<<<(E + T - 1) / T, T>>>(src, dst, fillc, colA, E);
    // 8: gather layer 1
    gather_kernel<128><<<(Nn * 16 + T - 1) / T, T>>>(X, rowptr, colA, AGG, Nn);

    // Layer 2
    gemm_mma_kernel<128, 64, 1, 3><<<grid23, T, smem2>>>(AGG, Wh + W2_OFF, Wl + W2_OFF,
                                                         b1, onrm, inrm, X, Nn, ntiles);
    gather_kernel<64><<<(Nn * 8 + T - 1) / T, T>>>(X, rowptr, colA, AGG, Nn);

    // Layer 3
    gemm_mma_kernel<64, 64, 1, 3><<<grid23, T, smem3>>>(AGG, Wh + W3_OFF, Wl + W3_OFF,
                                                        b2, onrm, inrm, X, Nn, ntiles);
    gather_kernel<64><<<(Nn * 8 + T - 1) / T, T>>>(X, rowptr, colA, AGG, Nn);

    // Pool
    pool_kernel<<<G, T>>>(AGG, inrm, b3, gid, out, Nn);
}

// round 16
// speedup vs baseline: 1.2700x; 1.0065x over previous
#include <cuda_runtime.h>
#include <cuda_bf16.h>
#include <cuda_fp16.h>
#include <cstdint>

// ---------------------------------------------------------------------------
// GCN: 3x (pointwise -> fp16x2 mma.sync GEMM -> CSR gather-sum) + mean pool
// R15->R16: same graph-level concurrency as R15, with the capture-legal
// fork: s2 waits on an event recorded in the origin stream BEFORE its first
// launch (R15 failed capture because s2 work was un-forked). Norms inline.
// ---------------------------------------------------------------------------

#define MAX_NODES 100000
#define MAX_EDGES 1600000
#define MAX_FEATS 128
#define SCAN_BS 512
#define NSM 148

__device__ __half g_EMB16[MAX_NODES * MAX_FEATS]; // emb converted to fp16
__device__ __half g_X[MAX_NODES * MAX_FEATS];     // GEMM outputs, fp16
__device__ __half g_AGG[MAX_NODES * MAX_FEATS];   // gathered sums, fp16
__device__ int    g_indeg[MAX_NODES];
__device__ int    g_outdeg[MAX_NODES];
__device__ int    g_rowptr[MAX_NODES + 1];
__device__ int    g_fill[MAX_NODES];
__device__ int    g_col[MAX_EDGES];
__device__ int    g_bsums[(MAX_NODES + SCAN_BS - 1) / SCAN_BS];
// Pre-split transposed weights (n-major, K contiguous), fp16 hi/lo: W1|W2|W3
__device__ __align__(16) __half g_Wh[28672];
__device__ __align__(16) __half g_Wl[28672];
#define W2_OFF 16384
#define W3_OFF 24576

// ----------------------------- helpers -------------------------------------

__device__ __forceinline__ uint32_t smem_u32(const void* p) {
    uint32_t a;
    asm("{ .reg .u64 t; cvta.to.shared.u64 t, %1; cvt.u32.u64 %0, t; }" : "=r"(a) : "l"(p));
    return a;
}

__device__ __forceinline__ void ldsm_x4(uint32_t* r, uint32_t addr) {
    asm volatile("ldmatrix.sync.aligned.m8n8.x4.shared.b16 {%0,%1,%2,%3}, [%4];"
                 : "=r"(r[0]), "=r"(r[1]), "=r"(r[2]), "=r"(r[3]) : "r"(addr));
}

__device__ __forceinline__ void mma_fp16(float* d, const uint32_t* a, const uint32_t* b) {
    asm volatile("mma.sync.aligned.m16n8k16.row.col.f32.f16.f16.f32 "
                 "{%0,%1,%2,%3}, {%4,%5,%6,%7}, {%8,%9}, {%0,%1,%2,%3};"
                 : "+f"(d[0]), "+f"(d[1]), "+f"(d[2]), "+f"(d[3])
                 : "r"(a[0]), "r"(a[1]), "r"(a[2]), "r"(a[3]), "r"(b[0]), "r"(b[1]));
}

__device__ __forceinline__ float deg_norm(int d) {
    return rsqrtf(fmaxf((float)d, 1.0f));
}

// ----------------- prep_conv: emb->fp16 + W split (stream s2) --------------

__global__ void prep_conv_kernel(const float* __restrict__ emb, __half* __restrict__ emb16,
                                 const float* __restrict__ W1, const float* __restrict__ W2,
                                 const float* __restrict__ W3,
                                 __half* __restrict__ Wh, __half* __restrict__ Wl,
                                 int ec4) {
    int i = blockIdx.x * blockDim.x + threadIdx.x;
    if (i < ec4) {
        float4 v = *reinterpret_cast<const float4*>(emb + (size_t)i * 4);
        __half2 h0 = __floats2half2_rn(v.x, v.y);
        __half2 h1 = __floats2half2_rn(v.z, v.w);
        uint2 o;
        o.x = reinterpret_cast<uint32_t&>(h0);
        o.y = reinterpret_cast<uint32_t&>(h1);
        *reinterpret_cast<uint2*>(emb16 + (size_t)i * 4) = o;
    }
    if (i < 128 * 128) {
        int nn = i >> 7, k = i & 127;
        float w = W1[k * 128 + nn];
        __half h = __float2half_rn(w);
        Wh[i] = h;
        Wl[i] = __float2half_rn(w - __half2float(h));
    }
    if (i < 64 * 128) {
        int nn = i >> 7, k = i & 127;
        float w = W2[k * 64 + nn];
        __half h = __float2half_rn(w);
        Wh[W2_OFF + i] = h;
        Wl[W2_OFF + i] = __float2half_rn(w - __half2float(h));
    }
    if (i < 64 * 64) {
        int nn = i >> 6, k = i & 63;
        float w = W3[k * 64 + nn];
        __half h = __float2half_rn(w);
        Wh[W3_OFF + i] = h;
        Wl[W3_OFF + i] = __float2half_rn(w - __half2float(h));
    }
}

// --------------------------- CSR construction ------------------------------

__global__ void zero_deg_kernel(int* __restrict__ a, int* __restrict__ b, int n) {
    int i = blockIdx.x * blockDim.x + threadIdx.x;
    if (i < n) { a[i] = 0; b[i] = 0; }
}

__global__ void hist_kernel(const int* __restrict__ src, const int* __restrict__ dst,
                            int* __restrict__ outdeg, int* __restrict__ indeg, int E) {
    int i = blockIdx.x * blockDim.x + threadIdx.x;
    if (i < E) {
        atomicAdd(outdeg + src[i], 1);
        atomicAdd(indeg + dst[i], 1);
    }
}

__global__ void scanA_kernel(const int* __restrict__ deg, int* __restrict__ rowptr,
                             int* __restrict__ bsums, int n) {
    __shared__ int sh[SCAN_BS];
    int t = threadIdx.x;
    int i = blockIdx.x * SCAN_BS + t;
    int v = (i < n) ? deg[i] : 0;
    sh[t] = v;
    __syncthreads();
#pragma unroll
    for (int off = 1; off < SCAN_BS; off <<= 1) {
        int x = (t >= off) ? sh[t - off] : 0;
        __syncthreads();
        sh[t] += x;
        __syncthreads();
    }
    if (i < n) rowptr[i] = sh[t] - v;
    if (t == SCAN_BS - 1) bsums[blockIdx.x] = sh[t];
}

__global__ void scanBC_kernel(int* __restrict__ rowptr, int* __restrict__ fill,
                              const int* __restrict__ bsums, int nb, int n, int E) {
    __shared__ int pref[256];
    int t = threadIdx.x;
    int v = (t < nb) ? bsums[t] : 0;
    pref[t] = v;
    __syncthreads();
#pragma unroll
    for (int off = 1; off < 256; off <<= 1) {
        int x = (t >= off) ? pref[t - off] : 0;
        __syncthreads();
        pref[t] += x;
        __syncthreads();
    }
    int i = blockIdx.x * blockDim.x + t;
    if (i < n) {
        int b = i / SCAN_BS;
        int excl = pref[b] - bsums[b];
        int r = rowptr[i] + excl;
        rowptr[i] = r;
        fill[i] = r;
    }
    if (i == 0) rowptr[n] = E;
}

__global__ void fill_kernel(const int* __restrict__ src, const int* __restrict__ dst,
                            int* __restrict__ fill, int* __restrict__ col, int E) {
    int i = blockIdx.x * blockDim.x + threadIdx.x;
    if (i < E) {
        int p = atomicAdd(fill + dst[i], 1);
        col[p] = src[i];
    }
}

// --------------------------- fp16x2 GEMM (persistent) ----------------------
// X[M,N] (fp16) = f(A[M,K]) @ W[K,N]; 256 threads (2x4 warps), OCC CTAs/SM.
// Full W (fp16 hi/lo) loaded to smem ONCE per CTA; CTA grid-strides over
// 64-row tiles; only A chunk (BK=32) is double-buffered. Norms inline.
// MODE 0: f(a)[r,k] = a[r,k] * outnorm[r]
// MODE 1: f(a)[r,k] = relu(a[r,k]*innorm[r] + bprev[k]) * outnorm[r]

template<int K, int N, int MODE, int OCC>
__global__ __launch_bounds__(256, OCC)
void gemm_mma_kernel(const __half* __restrict__ Ain,
                     const __half* __restrict__ Wh,
                     const __half* __restrict__ Wl,
                     const float* __restrict__ bprev,
                     const int* __restrict__ outdeg, const int* __restrict__ indeg,
                     __half* __restrict__ X, int M, int ntiles) {
    constexpr int BK = 32;
    constexpr int NCHUNK = K / BK;
    constexpr int WN = N / 4;
    constexpr int NT = WN / 8;
    constexpr int MT = 2;
    constexpr int P = 40;
    constexpr int KP = K + 8;
    constexpr int A_SZ = 64 * P * 2;
    constexpr int W_OFF = 2 * A_SZ;
    constexpr int W_SZ = N * KP * 2;
    constexpr int K8 = K / 8;

    extern __shared__ char smem[];
    const uint32_t sb = smem_u32(smem);
    const int tid = threadIdx.x;
    const int lane = tid & 31;
    const int wid = tid >> 5;
    const int warp_m = wid >> 2;
    const int warp_n = wid & 3;

    for (int idx = tid; idx < N * K8; idx += 256) {
        const int wn = idx / K8;
        const int wk8 = idx % K8;
        const size_t goff = (size_t)wn * K + wk8 * 8;
        uint4 h = *reinterpret_cast<const uint4*>(Wh + goff);
        uint4 l = *reinterpret_cast<const uint4*>(Wl + goff);
        const uint32_t off = (uint32_t)wn * (KP * 2) + wk8 * 16;
        *reinterpret_cast<uint4*>(smem + W_OFF + off) = h;
        *reinterpret_cast<uint4*>(smem + W_OFF + W_SZ + off) = l;
    }

    const int arow = tid & 63;
    const int aq = tid >> 6;
    const int col0 = aq * 8;

    const int a_r = warp_m * 32 + ((lane >> 3) & 1) * 8 + (lane & 7);
    const int a_k = (lane >> 4) * 8;
    const int b_n = warp_n * WN + (lane >> 4) * 8 + (lane & 7);
    const int b_k = ((lane >> 3) & 1) * 8;

    int grow = 0;
    bool valid = false;
    float on = 0.f, inn = 0.f;
    float a8[8];
    float acc[MT][NT][4];

    auto load_g = [&](int c) {
        const int kc = c * BK;
        uint4 u = make_uint4(0u, 0u, 0u, 0u);
        if (valid)
            u = *reinterpret_cast<const uint4*>(Ain + (size_t)grow * K + kc + col0);
        const __half2* hp = reinterpret_cast<const __half2*>(&u);
        float2 f0 = __half22float2(hp[0]);
        float2 f1 = __half22float2(hp[1]);
        float2 f2 = __half22float2(hp[2]);
        float2 f3 = __half22float2(hp[3]);
        if (MODE == 0) {
            a8[0] = f0.x * on; a8[1] = f0.y * on;
            a8[2] = f1.x * on; a8[3] = f1.y * on;
            a8[4] = f2.x * on; a8[5] = f2.y * on;
            a8[6] = f3.x * on; a8[7] = f3.y * on;
        } else {
            float4 b0 = *reinterpret_cast<const float4*>(bprev + kc + col0);
            float4 b1 = *reinterpret_cast<const float4*>(bprev + kc + col0 + 4);
            a8[0] = fmaxf(fmaf(f0.x, inn, b0.x), 0.f) * on;
            a8[1] = fmaxf(fmaf(f0.y, inn, b0.y), 0.f) * on;
            a8[2] = fmaxf(fmaf(f1.x, inn, b0.z), 0.f) * on;
            a8[3] = fmaxf(fmaf(f1.y, inn, b0.w), 0.f) * on;
            a8[4] = fmaxf(fmaf(f2.x, inn, b1.x), 0.f) * on;
            a8[5] = fmaxf(fmaf(f2.y, inn, b1.y), 0.f) * on;
            a8[6] = fmaxf(fmaf(f3.x, inn, b1.z), 0.f) * on;
            a8[7] = fmaxf(fmaf(f3.y, inn, b1.w), 0.f) * on;
        }
    };

    auto store_s = [&](int buf) {
        char* base = smem + buf * A_SZ;
        __half2 h0 = __floats2half2_rn(a8[0], a8[1]);
        __half2 h1 = __floats2half2_rn(a8[2], a8[3]);
        __half2 h2 = __floats2half2_rn(a8[4], a8[5]);
        __half2 h3 = __floats2half2_rn(a8[6], a8[7]);
        uint4 av4;
        av4.x = reinterpret_cast<uint32_t&>(h0);
        av4.y = reinterpret_cast<uint32_t&>(h1);
        av4.z = reinterpret_cast<uint32_t&>(h2);
        av4.w = reinterpret_cast<uint32_t&>(h3);
        const uint32_t aoff = (uint32_t)arow * (P * 2) + col0 * 2;
        *reinterpret_cast<uint4*>(base + aoff) = av4;
    };

    auto compute = [&](int buf, int c) {
        const uint32_t aB = sb + buf * A_SZ;
        const uint32_t wB = sb + W_OFF;
        const int kchunk = c * BK;
#pragma unroll
        for (int ks = 0; ks < 2; ks++) {
            uint32_t ah[MT][4];
#pragma unroll
            for (int i = 0; i < MT; i++) {
                const uint32_t addr = aB +
                    (uint32_t)(a_r + i * 16) * (P * 2) + (a_k + ks * 16) * 2;
                ldsm_x4(ah[i], addr);
            }
#pragma unroll
            for (int p = 0; p < NT / 2; p++) {
                uint32_t bh[4], bl[4];
                const uint32_t baddr = wB +
                    (uint32_t)(b_n + p * 16) * (KP * 2) +
                    (kchunk + b_k + ks * 16) * 2;
                ldsm_x4(bh, baddr);
                ldsm_x4(bl, baddr + W_SZ);
#pragma unroll
                for (int i = 0; i < MT; i++)
#pragma unroll
                    for (int jj = 0; jj < 2; jj++) {
                        float* d = acc[i][p * 2 + jj];
                        mma_fp16(d, ah[i], bh + jj * 2);
                        mma_fp16(d, ah[i], bl + jj * 2);
                    }
            }
        }
    };

    for (int tile = blockIdx.x; tile < ntiles; tile += gridDim.x) {
        const int row0 = tile * 64;
        grow = row0 + arow;
        valid = grow < M;
        on  = valid ? deg_norm(outdeg[grow]) : 0.f;
        inn = (MODE == 1 && valid) ? deg_norm(indeg[grow]) : 0.f;

#pragma unroll
        for (int i = 0; i < MT; i++)
#pragma unroll
            for (int j = 0; j < NT; j++)
#pragma unroll
                for (int q = 0; q < 4; q++) acc[i][j][q] = 0.f;

        load_g(0);
        store_s(0);
        __syncthreads();

        for (int c = 0; c < NCHUNK; c++) {
            if (c + 1 < NCHUNK) load_g(c + 1);
            compute(c & 1, c);
            if (c + 1 < NCHUNK) store_s((c + 1) & 1);
            __syncthreads();
        }

#pragma unroll
        for (int i = 0; i < MT; i++) {
            const int r0 = row0 + warp_m * 32 + i * 16 + (lane >> 2);
#pragma unroll
            for (int j = 0; j < NT; j++) {
                const int n0 = warp_n * WN + j * 8 + (lane & 3) * 2;
                if (r0 < M)
                    *reinterpret_cast<__half2*>(X + (size_t)r0 * N + n0) =
                        __floats2half2_rn(acc[i][j][0], acc[i][j][1]);
                if (r0 + 8 < M)
                    *reinterpret_cast<__half2*>(X + (size_t)(r0 + 8) * N + n0) =
                        __floats2half2_rn(acc[i][j][2], acc[i][j][3]);
            }
        }
    }
}

// ------------------------------ CSR gather ---------------------------------

template<int D>
__global__ __launch_bounds__(256)
void gather_kernel(const __half* __restrict__ X, const int* __restrict__ rowptr,
                   const int* __restrict__ col, __half* __restrict__ AGG, int Nn) {
    constexpr int LPN = D / 8;
    int t = blockIdx.x * blockDim.x + threadIdx.x;
    int node = t / LPN;
    if (node >= Nn) return;
    int c = (t % LPN) * 8;
    int beg = __ldg(rowptr + node);
    int end = __ldg(rowptr + node + 1);

    float a0[8], a1[8];
#pragma unroll
    for (int q = 0; q < 8; q++) { a0[q] = 0.f; a1[q] = 0.f; }

    int e = beg;
    for (; e + 1 < end; e += 2) {
        int s0 = __ldg(col + e);
        int s1 = __ldg(col + e + 1);
        uint4 u0 = __ldg(reinterpret_cast<const uint4*>(X + (size_t)s0 * D + c));
        uint4 u1 = __ldg(reinterpret_cast<const uint4*>(X + (size_t)s1 * D + c));
        const __half2* h0 = reinterpret_cast<const __half2*>(&u0);
        const __half2* h1 = reinterpret_cast<const __half2*>(&u1);
#pragma unroll
        for (int q = 0; q < 4; q++) {
            float2 f0 = __half22float2(h0[q]);
            float2 f1 = __half22float2(h1[q]);
            a0[q * 2]     += f0.x;
            a0[q * 2 + 1] += f0.y;
            a1[q * 2]     += f1.x;
            a1[q * 2 + 1] += f1.y;
        }
    }
    if (e < end) {
        int s0 = __ldg(col + e);
        uint4 u0 = __ldg(reinterpret_cast<const uint4*>(X + (size_t)s0 * D + c));
        const __half2* h0 = reinterpret_cast<const __half2*>(&u0);
#pragma unroll
        for (int q = 0; q < 4; q++) {
            float2 f0 = __half22float2(h0[q]);
            a0[q * 2]     += f0.x;
            a0[q * 2 + 1] += f0.y;
        }
    }

    __half2 o0 = __floats2half2_rn(a0[0] + a1[0], a0[1] + a1[1]);
    __half2 o1 = __floats2half2_rn(a0[2] + a1[2], a0[3] + a1[3]);
    __half2 o2 = __floats2half2_rn(a0[4] + a1[4], a0[5] + a1[5]);
    __half2 o3 = __floats2half2_rn(a0[6] + a1[6], a0[7] + a1[7]);
    uint4 out;
    out.x = reinterpret_cast<uint32_t&>(o0);
    out.y = reinterpret_cast<uint32_t&>(o1);
    out.z = reinterpret_cast<uint32_t&>(o2);
    out.w = reinterpret_cast<uint32_t&>(o3);
    *reinterpret_cast<uint4*>(AGG + (size_t)node * D + c) = out;
}

// ------------------------------- pooling -----------------------------------

__device__ __forceinline__ int lower_bound_dev(const int* __restrict__ a, int n, int v) {
    int lo = 0, hi = n;
    while (lo < hi) {
        int m = (lo + hi) >> 1;
        if (a[m] < v) lo = m + 1; else hi = m;
    }
    return lo;
}

__global__ void pool_kernel(const __half* __restrict__ AGG, const int* __restrict__ indeg,
                            const float* __restrict__ b3, const int* __restrict__ gids,
                            float* __restrict__ out, int Nn) {
    int g = blockIdx.x;
    int lo = lower_bound_dev(gids, Nn, g);
    int hi = lower_bound_dev(gids, Nn, g + 1);
    int f = threadIdx.x & 63;
    int slot = threadIdx.x >> 6;
    float bf = b3[f];
    float sum = 0.f;
    for (int i = lo + slot; i < hi; i += 4)
        sum += fmaf(__half2float(AGG[(size_t)i * 64 + f]),
                    deg_norm(indeg[i]), bf);
    __shared__ float sh[256];
    sh[threadIdx.x] = sum;
    __syncthreads();
    if (slot == 0) {
        float tot = sh[f] + sh[64 + f] + sh[128 + f] + sh[192 + f];
        float cnt = (float)(hi - lo);
        out[g * 64 + f] = tot / fmaxf(cnt, 1.f);
    }
}

// ------------------------------- launch ------------------------------------

extern "C" void kernel_launch(void* const* d_in, const int* in_sizes, int n_in,
                              void* d_out, int out_size) {
    const float* emb = (const float*)d_in[0];
    const float* W1  = (const float*)d_in[1];
    const float* b1  = (const float*)d_in[2];
    const float* W2  = (const float*)d_in[3];
    const float* b2  = (const float*)d_in[4];
    const float* W3  = (const float*)d_in[5];
    const float* b3  = (const float*)d_in[6];
    const int*   src = (const int*)d_in[7];
    const int*   dst = (const int*)d_in[8];
    const int*   gid = (const int*)d_in[9];
    float* out = (float*)d_out;

    const int Nn = in_sizes[0] / 128;   // 100000
    const int E  = in_sizes[7];         // 1600000
    const int G  = out_size / 64;       // 64

    __half *EMB16, *X, *AGG, *Wh, *Wl;
    int *indeg, *outdeg, *rowptr, *fillc, *colA, *bsums;
    cudaGetSymbolAddress((void**)&EMB16,  g_EMB16);
    cudaGetSymbolAddress((void**)&X,      g_X);
    cudaGetSymbolAddress((void**)&AGG,    g_AGG);
    cudaGetSymbolAddress((void**)&indeg,  g_indeg);
    cudaGetSymbolAddress((void**)&outdeg, g_outdeg);
    cudaGetSymbolAddress((void**)&rowptr, g_rowptr);
    cudaGetSymbolAddress((void**)&fillc,  g_fill);
    cudaGetSymbolAddress((void**)&colA,   g_col);
    cudaGetSymbolAddress((void**)&bsums,  g_bsums);
    cudaGetSymbolAddress((void**)&Wh,     g_Wh);
    cudaGetSymbolAddress((void**)&Wl,     g_Wl);

    const int smem1 = 2 * 5120 + 2 * 128 * 136 * 2;   // 79872
    const int smem2 = 2 * 5120 + 2 * 64 * 136 * 2;    // 45056
    const int smem3 = 2 * 5120 + 2 * 64 * 72 * 2;     // 28672
    cudaFuncSetAttribute(gemm_mma_kernel<128, 128, 0, 2>,
                         cudaFuncAttributeMaxDynamicSharedMemorySize, smem1);
    cudaFuncSetAttribute(gemm_mma_kernel<128, 64, 1, 3>,
                         cudaFuncAttributeMaxDynamicSharedMemorySize, smem2);
    cudaFuncSetAttribute(gemm_mma_kernel<64, 64, 1, 3>,
                         cudaFuncAttributeMaxDynamicSharedMemorySize, smem3);

    // side stream + events (host objects, created once on the first
    // uncaptured correctness call, reused afterwards)
    static cudaStream_t s2 = nullptr;
    static cudaEvent_t eFork = nullptr, ePrep = nullptr, eHist = nullptr, eFill = nullptr;
    if (!s2) {
        cudaStreamCreateWithFlags(&s2, cudaStreamNonBlocking);
        cudaEventCreateWithFlags(&eFork, cudaEventDisableTiming);
        cudaEventCreateWithFlags(&ePrep, cudaEventDisableTiming);
        cudaEventCreateWithFlags(&eHist, cudaEventDisableTiming);
        cudaEventCreateWithFlags(&eFill, cudaEventDisableTiming);
    }

    const int T = 256;
    const int ntiles = (Nn + 63) / 64;
    const int grid1 = (ntiles < NSM * 2) ? ntiles : NSM * 2;
    const int grid23 = (ntiles < NSM * 3) ? ntiles : NSM * 3;
    const int nb_scan = (Nn + SCAN_BS - 1) / SCAN_BS;
    const int ec4 = Nn * 32;

    // --- capture-legal fork: s2 joins the capture via eFork from stream 0 ---
    cudaEventRecord(eFork, 0);
    cudaStreamWaitEvent(s2, eFork, 0);

    // --- s2: prep_conv (independent of degrees) ---
    prep_conv_kernel<<<(ec4 + T - 1) / T, T, 0, s2>>>(emb, EMB16, W1, W2, W3,
                                                      Wh, Wl, ec4);
    cudaEventRecord(ePrep, s2);

    // --- main stream: degrees ---
    zero_deg_kernel<<<(Nn + T - 1) / T, T>>>(indeg, outdeg, Nn);
    hist_kernel<<<(E + T - 1) / T, T>>>(src, dst, outdeg, indeg, E);
    cudaEventRecord(eHist, 0);

    // --- main: GEMM1 (4th kernel launch -> ncu slot); needs prep + degrees ---
    cudaStreamWaitEvent(0, ePrep, 0);
    gemm_mma_kernel<128, 128, 0, 2><<<grid1, T, smem1>>>(EMB16, Wh, Wl, nullptr,
                                                         outdeg, indeg, X, Nn, ntiles);

    // --- s2: CSR build concurrent with GEMM1 ---
    cudaStreamWaitEvent(s2, eHist, 0);
    scanA_kernel<<<nb_scan, SCAN_BS, 0, s2>>>(indeg, rowptr, bsums, Nn);
    scanBC_kernel<<<(Nn + 255) / 256, 256, 0, s2>>>(rowptr, fillc, bsums, nb_scan, Nn, E);
    fill_kernel<<<(E + T - 1) / T, T, 0, s2>>>(src, dst, fillc, colA, E);
    cudaEventRecord(eFill, s2);

    // --- join: gather1 needs CSR + X1; s2 fully joined before capture ends ---
    cudaStreamWaitEvent(0, eFill, 0);
    gather_kernel<128><<<(Nn * 16 + T - 1) / T, T>>>(X, rowptr, colA, AGG, Nn);

    // Layer 2
    gemm_mma_kernel<128, 64, 1, 3><<<grid23, T, smem2>>>(AGG, Wh + W2_OFF, Wl + W2_OFF,
                                                         b1, outdeg, indeg, X, Nn, ntiles);
    gather_kernel<64><<<(Nn * 8 + T - 1) / T, T>>>(X, rowptr, colA, AGG, Nn);

    // Layer 3
    gemm_mma_kernel<64, 64, 1, 3><<<grid23, T, smem3>>>(AGG, Wh + W3_OFF, Wl + W3_OFF,
                                                        b2, outdeg, indeg, X, Nn, ntiles);
    gather_kernel<64><<<(Nn * 8 + T - 1) / T, T>>>(X, rowptr, colA, AGG, Nn);

    // Pool
    pool_kernel<<<G, T>>>(AGG, indeg, b3, gid, out, Nn);
}

// round 17
// speedup vs baseline: 1.3164x; 1.0366x over previous
#include <cuda_runtime.h>
#include <cuda_bf16.h>
#include <cuda_fp16.h>
#include <cstdint>

// ---------------------------------------------------------------------------
// GCN: 3x (fp16x2 cp.async GEMM -> CSR gather(+fused pointwise)) + mean pool
// R16->R17: pointwise moved OUT of GEMM A-path: outnorm -> GEMM epilogue
// (row scaling commutes with @W); relu/bias/innorm/outnorm for layers 2,3 ->
// gather epilogue (per-node ops on fp32 sums). GEMM A-load is now a pure
// cp.async.cg 16B copy with a 3-stage pipeline (was LDG+cvt+STS per chunk).
// ---------------------------------------------------------------------------

#define MAX_NODES 100000
#define MAX_EDGES 1600000
#define MAX_FEATS 128
#define SCAN_BS 512
#define NSM 148

__device__ __half g_EMB16[MAX_NODES * MAX_FEATS]; // emb converted to fp16
__device__ __half g_X[MAX_NODES * MAX_FEATS];     // GEMM outputs, fp16
__device__ __half g_AGG[MAX_NODES * MAX_FEATS];   // gathered (+transformed) sums
__device__ int    g_indeg[MAX_NODES];
__device__ int    g_outdeg[MAX_NODES];
__device__ int    g_rowptr[MAX_NODES + 1];
__device__ int    g_fill[MAX_NODES];
__device__ int    g_col[MAX_EDGES];
__device__ int    g_bsums[(MAX_NODES + SCAN_BS - 1) / SCAN_BS];
// Pre-split transposed weights (n-major, K contiguous), fp16 hi/lo: W1|W2|W3
__device__ __align__(16) __half g_Wh[28672];
__device__ __align__(16) __half g_Wl[28672];
#define W2_OFF 16384
#define W3_OFF 24576

// ----------------------------- helpers -------------------------------------

__device__ __forceinline__ uint32_t smem_u32(const void* p) {
    uint32_t a;
    asm("{ .reg .u64 t; cvta.to.shared.u64 t, %1; cvt.u32.u64 %0, t; }" : "=r"(a) : "l"(p));
    return a;
}

__device__ __forceinline__ void ldsm_x4(uint32_t* r, uint32_t addr) {
    asm volatile("ldmatrix.sync.aligned.m8n8.x4.shared.b16 {%0,%1,%2,%3}, [%4];"
                 : "=r"(r[0]), "=r"(r[1]), "=r"(r[2]), "=r"(r[3]) : "r"(addr));
}

__device__ __forceinline__ void mma_fp16(float* d, const uint32_t* a, const uint32_t* b) {
    asm volatile("mma.sync.aligned.m16n8k16.row.col.f32.f16.f16.f32 "
                 "{%0,%1,%2,%3}, {%4,%5,%6,%7}, {%8,%9}, {%0,%1,%2,%3};"
                 : "+f"(d[0]), "+f"(d[1]), "+f"(d[2]), "+f"(d[3])
                 : "r"(a[0]), "r"(a[1]), "r"(a[2]), "r"(a[3]), "r"(b[0]), "r"(b[1]));
}

__device__ __forceinline__ void cp_async16(uint32_t dst, const void* src, int bytes) {
    asm volatile("cp.async.cg.shared.global [%0], [%1], 16, %2;"
                 :: "r"(dst), "l"(src), "r"(bytes));
}
#define CP_COMMIT() asm volatile("cp.async.commit_group;" ::: "memory")
#define CP_WAIT1()  asm volatile("cp.async.wait_group 1;" ::: "memory")
#define CP_WAIT0()  asm volatile("cp.async.wait_group 0;" ::: "memory")

__device__ __forceinline__ float deg_norm(int d) {
    return rsqrtf(fmaxf((float)d, 1.0f));
}

// ----------------- prep_conv: emb->fp16 + W split (stream s2) --------------

__global__ void prep_conv_kernel(const float* __restrict__ emb, __half* __restrict__ emb16,
                                 const float* __restrict__ W1, const float* __restrict__ W2,
                                 const float* __restrict__ W3,
                                 __half* __restrict__ Wh, __half* __restrict__ Wl,
                                 int ec4) {
    int i = blockIdx.x * blockDim.x + threadIdx.x;
    if (i < ec4) {
        float4 v = *reinterpret_cast<const float4*>(emb + (size_t)i * 4);
        __half2 h0 = __floats2half2_rn(v.x, v.y);
        __half2 h1 = __floats2half2_rn(v.z, v.w);
        uint2 o;
        o.x = reinterpret_cast<uint32_t&>(h0);
        o.y = reinterpret_cast<uint32_t&>(h1);
        *reinterpret_cast<uint2*>(emb16 + (size_t)i * 4) = o;
    }
    if (i < 128 * 128) {
        int nn = i >> 7, k = i & 127;
        float w = W1[k * 128 + nn];
        __half h = __float2half_rn(w);
        Wh[i] = h;
        Wl[i] = __float2half_rn(w - __half2float(h));
    }
    if (i < 64 * 128) {
        int nn = i >> 7, k = i & 127;
        float w = W2[k * 64 + nn];
        __half h = __float2half_rn(w);
        Wh[W2_OFF + i] = h;
        Wl[W2_OFF + i] = __float2half_rn(w - __half2float(h));
    }
    if (i < 64 * 64) {
        int nn = i >> 6, k = i & 63;
        float w = W3[k * 64 + nn];
        __half h = __float2half_rn(w);
        Wh[W3_OFF + i] = h;
        Wl[W3_OFF + i] = __float2half_rn(w - __half2float(h));
    }
}

// --------------------------- CSR construction ------------------------------

__global__ void zero_deg_kernel(int* __restrict__ a, int* __restrict__ b, int n) {
    int i = blockIdx.x * blockDim.x + threadIdx.x;
    if (i < n) { a[i] = 0; b[i] = 0; }
}

__global__ void hist_kernel(const int* __restrict__ src, const int* __restrict__ dst,
                            int* __restrict__ outdeg, int* __restrict__ indeg, int E) {
    int i = blockIdx.x * blockDim.x + threadIdx.x;
    if (i < E) {
        atomicAdd(outdeg + src[i], 1);
        atomicAdd(indeg + dst[i], 1);
    }
}

__global__ void scanA_kernel(const int* __restrict__ deg, int* __restrict__ rowptr,
                             int* __restrict__ bsums, int n) {
    __shared__ int sh[SCAN_BS];
    int t = threadIdx.x;
    int i = blockIdx.x * SCAN_BS + t;
    int v = (i < n) ? deg[i] : 0;
    sh[t] = v;
    __syncthreads();
#pragma unroll
    for (int off = 1; off < SCAN_BS; off <<= 1) {
        int x = (t >= off) ? sh[t - off] : 0;
        __syncthreads();
        sh[t] += x;
        __syncthreads();
    }
    if (i < n) rowptr[i] = sh[t] - v;
    if (t == SCAN_BS - 1) bsums[blockIdx.x] = sh[t];
}

__global__ void scanBC_kernel(int* __restrict__ rowptr, int* __restrict__ fill,
                              const int* __restrict__ bsums, int nb, int n, int E) {
    __shared__ int pref[256];
    int t = threadIdx.x;
    int v = (t < nb) ? bsums[t] : 0;
    pref[t] = v;
    __syncthreads();
#pragma unroll
    for (int off = 1; off < 256; off <<= 1) {
        int x = (t >= off) ? pref[t - off] : 0;
        __syncthreads();
        pref[t] += x;
        __syncthreads();
    }
    int i = blockIdx.x * blockDim.x + t;
    if (i < n) {
        int b = i / SCAN_BS;
        int excl = pref[b] - bsums[b];
        int r = rowptr[i] + excl;
        rowptr[i] = r;
        fill[i] = r;
    }
    if (i == 0) rowptr[n] = E;
}

__global__ void fill_kernel(const int* __restrict__ src, const int* __restrict__ dst,
                            int* __restrict__ fill, int* __restrict__ col, int E) {
    int i = blockIdx.x * blockDim.x + threadIdx.x;
    if (i < E) {
        int p = atomicAdd(fill + dst[i], 1);
        col[p] = src[i];
    }
}

// --------------------- fp16x2 GEMM (persistent, cp.async) ------------------
// X[M,N] (fp16) = A[M,K] @ (Wh+Wl); 256 threads (2x4 warps), OCC CTAs/SM.
// Full W in smem once; A chunk (BK=32) via 3-stage cp.async pipeline.
// MODE 0: epilogue scales row r by outnorm[r]  (GEMM1)
// MODE 1: no pointwise at all (transform fused into producing gather)

template<int K, int N, int MODE, int OCC>
__global__ __launch_bounds__(256, OCC)
void gemm_mma_kernel(const __half* __restrict__ Ain,
                     const __half* __restrict__ Wh,
                     const __half* __restrict__ Wl,
                     const int* __restrict__ outdeg,
                     __half* __restrict__ X, int M, int ntiles) {
    constexpr int BK = 32;
    constexpr int NCHUNK = K / BK;
    constexpr int WN = N / 4;
    constexpr int NT = WN / 8;
    constexpr int MT = 2;
    constexpr int P = 40;                 // A smem pitch (halves), 80B
    constexpr int A_SZ = 64 * P * 2;      // 5120 per stage
    constexpr int W_OFF = 3 * A_SZ;       // 15360
    constexpr int KP = K + 8;
    constexpr int W_SZ = N * KP * 2;
    constexpr int K8 = K / 8;

    extern __shared__ char smem[];
    const uint32_t sb = smem_u32(smem);
    const int tid = threadIdx.x;
    const int lane = tid & 31;
    const int wid = tid >> 5;
    const int warp_m = wid >> 2;
    const int warp_n = wid & 3;

    // full W -> smem once
    for (int idx = tid; idx < N * K8; idx += 256) {
        const int wn = idx / K8;
        const int wk8 = idx % K8;
        const size_t goff = (size_t)wn * K + wk8 * 8;
        uint4 h = *reinterpret_cast<const uint4*>(Wh + goff);
        uint4 l = *reinterpret_cast<const uint4*>(Wl + goff);
        const uint32_t off = (uint32_t)wn * (KP * 2) + wk8 * 16;
        *reinterpret_cast<uint4*>(smem + W_OFF + off) = h;
        *reinterpret_cast<uint4*>(smem + W_OFF + W_SZ + off) = l;
    }

    const int arow = tid & 63;
    const int aq = tid >> 6;              // 0..3 -> 16B segment of the row
    const uint32_t a_dst = sb + (uint32_t)arow * (P * 2) + aq * 16;

    const int a_r = warp_m * 32 + ((lane >> 3) & 1) * 8 + (lane & 7);
    const int a_k = (lane >> 4) * 8;
    const int b_n = warp_n * WN + (lane >> 4) * 8 + (lane & 7);
    const int b_k = ((lane >> 3) & 1) * 8;

    int grow = 0;
    bool valid = false;
    float acc[MT][NT][4];

    auto issue = [&](int c) {
        cp_async16(a_dst + (c % 3) * A_SZ,
                   Ain + (size_t)grow * K + c * BK + aq * 8,
                   valid ? 16 : 0);
    };

    auto compute = [&](int c) {
        const uint32_t aB = sb + (c % 3) * A_SZ;
        const uint32_t wB = sb + W_OFF;
        const int kchunk = c * BK;
#pragma unroll
        for (int ks = 0; ks < 2; ks++) {
            uint32_t ah[MT][4];
#pragma unroll
            for (int i = 0; i < MT; i++) {
                const uint32_t addr = aB +
                    (uint32_t)(a_r + i * 16) * (P * 2) + (a_k + ks * 16) * 2;
                ldsm_x4(ah[i], addr);
            }
#pragma unroll
            for (int p = 0; p < NT / 2; p++) {
                uint32_t bh[4], bl[4];
                const uint32_t baddr = wB +
                    (uint32_t)(b_n + p * 16) * (KP * 2) +
                    (kchunk + b_k + ks * 16) * 2;
                ldsm_x4(bh, baddr);
                ldsm_x4(bl, baddr + W_SZ);
#pragma unroll
                for (int i = 0; i < MT; i++)
#pragma unroll
                    for (int jj = 0; jj < 2; jj++) {
                        float* d = acc[i][p * 2 + jj];
                        mma_fp16(d, ah[i], bh + jj * 2);
                        mma_fp16(d, ah[i], bl + jj * 2);
                    }
            }
        }
    };

    for (int tile = blockIdx.x; tile < ntiles; tile += gridDim.x) {
        const int row0 = tile * 64;
        grow = row0 + arow;
        valid = grow < M;

#pragma unroll
        for (int i = 0; i < MT; i++)
#pragma unroll
            for (int j = 0; j < NT; j++)
#pragma unroll
                for (int q = 0; q < 4; q++) acc[i][j][q] = 0.f;

        issue(0); CP_COMMIT();
        if (NCHUNK > 1) { issue(1); CP_COMMIT(); }

        for (int c = 0; c < NCHUNK; c++) {
            if (c + 1 < NCHUNK) { CP_WAIT1(); } else { CP_WAIT0(); }
            __syncthreads();
            compute(c);
            if (c + 2 < NCHUNK) { issue(c + 2); CP_COMMIT(); }
        }
        __syncthreads();   // all compute done before next tile reuses buffers

        // epilogue: fp32 acc (-> *outnorm for MODE 0) -> fp16 X
#pragma unroll
        for (int i = 0; i < MT; i++) {
            const int r0 = row0 + warp_m * 32 + i * 16 + (lane >> 2);
            float on0 = 1.f, on1 = 1.f;
            if (MODE == 0) {
                on0 = (r0 < M) ? deg_norm(outdeg[r0]) : 0.f;
                on1 = (r0 + 8 < M) ? deg_norm(outdeg[r0 + 8]) : 0.f;
            }
#pragma unroll
            for (int j = 0; j < NT; j++) {
                const int n0 = warp_n * WN + j * 8 + (lane & 3) * 2;
                if (r0 < M)
                    *reinterpret_cast<__half2*>(X + (size_t)r0 * N + n0) =
                        __floats2half2_rn(acc[i][j][0] * on0, acc[i][j][1] * on0);
                if (r0 + 8 < M)
                    *reinterpret_cast<__half2*>(X + (size_t)(r0 + 8) * N + n0) =
                        __floats2half2_rn(acc[i][j][2] * on1, acc[i][j][3] * on1);
            }
        }
    }
}

// ------------------------------ CSR gather ---------------------------------
// sums[n] = sum over e in [rowptr[n], rowptr[n+1]) of X[col[e]] (fp32 accum)
// TRANS=1: AGG[n] = relu(sums*innorm[n] + bias) * outnorm[n]   (next-layer A)
// TRANS=0: AGG[n] = sums (raw, for pool)

template<int D, int TRANS>
__global__ __launch_bounds__(256)
void gather_kernel(const __half* __restrict__ X, const int* __restrict__ rowptr,
                   const int* __restrict__ col,
                   const int* __restrict__ indeg, const int* __restrict__ outdeg,
                   const float* __restrict__ bias,
                   __half* __restrict__ AGG, int Nn) {
    constexpr int LPN = D / 8;
    int t = blockIdx.x * blockDim.x + threadIdx.x;
    int node = t / LPN;
    if (node >= Nn) return;
    int c = (t % LPN) * 8;
    int beg = __ldg(rowptr + node);
    int end = __ldg(rowptr + node + 1);

    float a0[8], a1[8];
#pragma unroll
    for (int q = 0; q < 8; q++) { a0[q] = 0.f; a1[q] = 0.f; }

    int e = beg;
    for (; e + 1 < end; e += 2) {
        int s0 = __ldg(col + e);
        int s1 = __ldg(col + e + 1);
        uint4 u0 = __ldg(reinterpret_cast<const uint4*>(X + (size_t)s0 * D + c));
        uint4 u1 = __ldg(reinterpret_cast<const uint4*>(X + (size_t)s1 * D + c));
        const __half2* h0 = reinterpret_cast<const __half2*>(&u0);
        const __half2* h1 = reinterpret_cast<const __half2*>(&u1);
#pragma unroll
        for (int q = 0; q < 4; q++) {
            float2 f0 = __half22float2(h0[q]);
            float2 f1 = __half22float2(h1[q]);
            a0[q * 2]     += f0.x;
            a0[q * 2 + 1] += f0.y;
            a1[q * 2]     += f1.x;
            a1[q * 2 + 1] += f1.y;
        }
    }
    if (e < end) {
        int s0 = __ldg(col + e);
        uint4 u0 = __ldg(reinterpret_cast<const uint4*>(X + (size_t)s0 * D + c));
        const __half2* h0 = reinterpret_cast<const __half2*>(&u0);
#pragma unroll
        for (int q = 0; q < 4; q++) {
            float2 f0 = __half22float2(h0[q]);
            a0[q * 2]     += f0.x;
            a0[q * 2 + 1] += f0.y;
        }
    }

    float s[8];
#pragma unroll
    for (int q = 0; q < 8; q++) s[q] = a0[q] + a1[q];

    if (TRANS) {
        float inn = deg_norm(__ldg(indeg + node));
        float on  = deg_norm(__ldg(outdeg + node));
        float4 b0 = *reinterpret_cast<const float4*>(bias + c);
        float4 b1 = *reinterpret_cast<const float4*>(bias + c + 4);
        s[0] = fmaxf(fmaf(s[0], inn, b0.x), 0.f) * on;
        s[1] = fmaxf(fmaf(s[1], inn, b0.y), 0.f) * on;
        s[2] = fmaxf(fmaf(s[2], inn, b0.z), 0.f) * on;
        s[3] = fmaxf(fmaf(s[3], inn, b0.w), 0.f) * on;
        s[4] = fmaxf(fmaf(s[4], inn, b1.x), 0.f) * on;
        s[5] = fmaxf(fmaf(s[5], inn, b1.y), 0.f) * on;
        s[6] = fmaxf(fmaf(s[6], inn, b1.z), 0.f) * on;
        s[7] = fmaxf(fmaf(s[7], inn, b1.w), 0.f) * on;
    }

    __half2 o0 = __floats2half2_rn(s[0], s[1]);
    __half2 o1 = __floats2half2_rn(s[2], s[3]);
    __half2 o2 = __floats2half2_rn(s[4], s[5]);
    __half2 o3 = __floats2half2_rn(s[6], s[7]);
    uint4 out;
    out.x = reinterpret_cast<uint32_t&>(o0);
    out.y = reinterpret_cast<uint32_t&>(o1);
    out.z = reinterpret_cast<uint32_t&>(o2);
    out.w = reinterpret_cast<uint32_t&>(o3);
    *reinterpret_cast<uint4*>(AGG + (size_t)node * D + c) = out;
}

// ------------------------------- pooling -----------------------------------

__device__ __forceinline__ int lower_bound_dev(const int* __restrict__ a, int n, int v) {
    int lo = 0, hi = n;
    while (lo < hi) {
        int m = (lo + hi) >> 1;
        if (a[m] < v) lo = m + 1; else hi = m;
    }
    return lo;
}

__global__ void pool_kernel(const __half* __restrict__ AGG, const int* __restrict__ indeg,
                            const float* __restrict__ b3, const int* __restrict__ gids,
                            float* __restrict__ out, int Nn) {
    int g = blockIdx.x;
    int lo = lower_bound_dev(gids, Nn, g);
    int hi = lower_bound_dev(gids, Nn, g + 1);
    int f = threadIdx.x & 63;
    int slot = threadIdx.x >> 6;
    float bf = b3[f];
    float sum = 0.f;
    for (int i = lo + slot; i < hi; i += 4)
        sum += fmaf(__half2float(AGG[(size_t)i * 64 + f]),
                    deg_norm(indeg[i]), bf);
    __shared__ float sh[256];
    sh[threadIdx.x] = sum;
    __syncthreads();
    if (slot == 0) {
        float tot = sh[f] + sh[64 + f] + sh[128 + f] + sh[192 + f];
        float cnt = (float)(hi - lo);
        out[g * 64 + f] = tot / fmaxf(cnt, 1.f);
    }
}

// ------------------------------- launch ------------------------------------

extern "C" void kernel_launch(void* const* d_in, const int* in_sizes, int n_in,
                              void* d_out, int out_size) {
    const float* emb = (const float*)d_in[0];
    const float* W1  = (const float*)d_in[1];
    const float* b1  = (const float*)d_in[2];
    const float* W2  = (const float*)d_in[3];
    const float* b2  = (const float*)d_in[4];
    const float* W3  = (const float*)d_in[5];
    const float* b3  = (const float*)d_in[6];
    const int*   src = (const int*)d_in[7];
    const int*   dst = (const int*)d_in[8];
    const int*   gid = (const int*)d_in[9];
    float* out = (float*)d_out;

    const int Nn = in_sizes[0] / 128;   // 100000
    const int E  = in_sizes[7];         // 1600000
    const int G  = out_size / 64;       // 64

    __half *EMB16, *X, *AGG, *Wh, *Wl;
    int *indeg, *outdeg, *rowptr, *fillc, *colA, *bsums;
    cudaGetSymbolAddress((void**)&EMB16,  g_EMB16);
    cudaGetSymbolAddress((void**)&X,      g_X);
    cudaGetSymbolAddress((void**)&AGG,    g_AGG);
    cudaGetSymbolAddress((void**)&indeg,  g_indeg);
    cudaGetSymbolAddress((void**)&outdeg, g_outdeg);
    cudaGetSymbolAddress((void**)&rowptr, g_rowptr);
    cudaGetSymbolAddress((void**)&fillc,  g_fill);
    cudaGetSymbolAddress((void**)&colA,   g_col);
    cudaGetSymbolAddress((void**)&bsums,  g_bsums);
    cudaGetSymbolAddress((void**)&Wh,     g_Wh);
    cudaGetSymbolAddress((void**)&Wl,     g_Wl);

    // smem: 3*A_SZ + 2*W_SZ
    const int smem1 = 3 * 5120 + 2 * 128 * 136 * 2;   // 84992
    const int smem2 = 3 * 5120 + 2 * 64 * 136 * 2;    // 50176
    const int smem3 = 3 * 5120 + 2 * 64 * 72 * 2;     // 33792
    cudaFuncSetAttribute(gemm_mma_kernel<128, 128, 0, 2>,
                         cudaFuncAttributeMaxDynamicSharedMemorySize, smem1);
    cudaFuncSetAttribute(gemm_mma_kernel<128, 64, 1, 3>,
                         cudaFuncAttributeMaxDynamicSharedMemorySize, smem2);
    cudaFuncSetAttribute(gemm_mma_kernel<64, 64, 1, 3>,
                         cudaFuncAttributeMaxDynamicSharedMemorySize, smem3);

    static cudaStream_t s2 = nullptr;
    static cudaEvent_t eFork = nullptr, ePrep = nullptr, eHist = nullptr, eFill = nullptr;
    if (!s2) {
        cudaStreamCreateWithFlags(&s2, cudaStreamNonBlocking);
        cudaEventCreateWithFlags(&eFork, cudaEventDisableTiming);
        cudaEventCreateWithFlags(&ePrep, cudaEventDisableTiming);
        cudaEventCreateWithFlags(&eHist, cudaEventDisableTiming);
        cudaEventCreateWithFlags(&eFill, cudaEventDisableTiming);
    }

    const int T = 256;
    const int ntiles = (Nn + 63) / 64;
    const int grid1 = (ntiles < NSM * 2) ? ntiles : NSM * 2;
    const int grid23 = (ntiles < NSM * 3) ? ntiles : NSM * 3;
    const int nb_scan = (Nn + SCAN_BS - 1) / SCAN_BS;
    const int ec4 = Nn * 32;

    // capture-legal fork
    cudaEventRecord(eFork, 0);
    cudaStreamWaitEvent(s2, eFork, 0);

    // s2: prep_conv
    prep_conv_kernel<<<(ec4 + T - 1) / T, T, 0, s2>>>(emb, EMB16, W1, W2, W3,
                                                      Wh, Wl, ec4);
    cudaEventRecord(ePrep, s2);

    // main: degrees
    zero_deg_kernel<<<(Nn + T - 1) / T, T>>>(indeg, outdeg, Nn);
    hist_kernel<<<(E + T - 1) / T, T>>>(src, dst, outdeg, indeg, E);
    cudaEventRecord(eHist, 0);

    // main: GEMM1 (4th kernel launch -> ncu slot)
    cudaStreamWaitEvent(0, ePrep, 0);
    gemm_mma_kernel<128, 128, 0, 2><<<grid1, T, smem1>>>(EMB16, Wh, Wl, outdeg,
                                                         X, Nn, ntiles);

    // s2: CSR build concurrent with GEMM1
    cudaStreamWaitEvent(s2, eHist, 0);
    scanA_kernel<<<nb_scan, SCAN_BS, 0, s2>>>(indeg, rowptr, bsums, Nn);
    scanBC_kernel<<<(Nn + 255) / 256, 256, 0, s2>>>(rowptr, fillc, bsums, nb_scan, Nn, E);
    fill_kernel<<<(E + T - 1) / T, T, 0, s2>>>(src, dst, fillc, colA, E);
    cudaEventRecord(eFill, s2);

    // join
    cudaStreamWaitEvent(0, eFill, 0);
    // gather1: X1 sums -> transformed A2 (inn, b1, relu, on)
    gather_kernel<128, 1><<<(Nn * 16 + T - 1) / T, T>>>(X, rowptr, colA,
                                                        indeg, outdeg, b1, AGG, Nn);

    // Layer 2: pure GEMM, then gather2 -> transformed A3 (b2)
    gemm_mma_kernel<128, 64, 1, 3><<<grid23, T, smem2>>>(AGG, Wh + W2_OFF, Wl + W2_OFF,
                                                         outdeg, X, Nn, ntiles);
    gather_kernel<64, 1><<<(Nn * 8 + T - 1) / T, T>>>(X, rowptr, colA,
                                                      indeg, outdeg, b2, AGG, Nn);

    // Layer 3: pure GEMM, then raw gather3
    gemm_mma_kernel<64, 64, 1, 3><<<grid23, T, smem3>>>(AGG, Wh + W3_OFF, Wl + W3_OFF,
                                                        outdeg, X, Nn, ntiles);
    gather_kernel<64, 0><<<(Nn * 8 + T - 1) / T, T>>>(X, rowptr, colA,
                                                      indeg, outdeg, nullptr, AGG, Nn);

    // Pool
    pool_kernel<<<G, T>>>(AGG, indeg, b3, gid, out, Nn);
}